// round 6
// baseline (speedup 1.0000x reference)
#include <cuda_runtime.h>
#include <cstdint>

#define Bb 2
#define Nn 1024
#define Dd 1024
#define Hh 16
#define DhC 64
#define Ss 64
#define DbC 512

// -------- scratch (static device globals) --------
__device__ float g_Q[Bb*Nn*Dd];
__device__ float g_K[Bb*Nn*Dd];
__device__ float g_V[Bb*Nn*Dd];
__device__ float g_G[Bb*Nn*Dd];
__device__ float g_std[Bb*Nn*Dd];
__device__ float g_infl[Bb*Nn*Ss];
__device__ float g_total[Bb*Ss];
__device__ float g_gath[Bb*Ss*Dd];
__device__ float g_enc[Bb*Ss*DbC];
__device__ float g_trans[Bb*Ss*DbC];
__device__ float g_dec[Bb*Ss*Dd];
__device__ float g_blend[Bb*Nn*Dd];

// ============================================================
// helpers
// ============================================================
__device__ __forceinline__ uint32_t f2tf32(float x) {
    uint32_t r;
    asm("cvt.rna.tf32.f32 %0, %1;" : "=r"(r) : "f"(x));
    return r;
}
__device__ __forceinline__ float tfhi(float x) {
    return __uint_as_float(__float_as_uint(x) & 0xFFFFE000u);
}
__device__ __forceinline__ float2 split2(float v) {
    float h = __uint_as_float(f2tf32(v));
    float l = __uint_as_float(f2tf32(v - h));
    return make_float2(h, l);
}
__device__ __forceinline__ void mma_tf32(float* c,
    uint32_t a0, uint32_t a1, uint32_t a2, uint32_t a3,
    uint32_t b0, uint32_t b1)
{
    asm volatile(
        "mma.sync.aligned.m16n8k8.row.col.f32.tf32.tf32.f32 "
        "{%0,%1,%2,%3},{%4,%5,%6,%7},{%8,%9},{%0,%1,%2,%3};"
        : "+f"(c[0]), "+f"(c[1]), "+f"(c[2]), "+f"(c[3])
        : "r"(a0), "r"(a1), "r"(a2), "r"(a3), "r"(b0), "r"(b1));
}
#define FU(x) __float_as_uint(x)

// ============================================================
// tf32 mma.sync GEMM v2: hi/lo pre-split at staging, interleaved
// float2 smem, LDS.64 fragment loads.
// C[M, segN] = A[M,K] @ B[K,segN] per segment (block-uniform seg).
// epi: 0=none, 1=sigmoid(+bias), 2=relu(+bias), 3=+bias
// ============================================================
struct GArgs {
    const float* A;
    const float* B[4];
    const float* bias[4];
    float*       C[4];
    int K;
    int segN;
    int epi[4];
};

#define SPAD2 132   // float2 row stride; 132 mod 16 == 4 -> conflict-free frags

__global__ __launch_bounds__(256, 2) void tf32_gemm(GArgs g)
{
    __shared__ float2 As2[16][SPAD2];   // As2[k][m] = (hi, lo)
    __shared__ float2 Bs2[16][SPAD2];   // Bs2[k][n] = (hi, lo)

    const int tid = threadIdx.x;
    const int warp = tid >> 5;
    const int lane = tid & 31;
    const int lr = lane >> 2;
    const int lc = lane & 3;
    const int wm = warp >> 2;
    const int wn = warp & 3;

    const int seg    = (blockIdx.x * 128) / g.segN;
    const int colSeg = (blockIdx.x * 128) % g.segN;
    const int rowBase = blockIdx.y * 128;
    const float* __restrict__ Bp   = g.B[seg];
    const float* __restrict__ bias = g.bias[seg];
    float* __restrict__ Cp         = g.C[seg];
    const int epi  = g.epi[seg];
    const int K    = g.K;
    const int segN = g.segN;

    const int aRow0 = tid >> 2;
    const int aCol0 = (tid & 3) << 2;
    const int bRow0 = tid >> 5;
    const int bCol0 = (tid & 31) << 2;

    float acc[4][4][4];
#pragma unroll
    for (int i = 0; i < 4; i++)
#pragma unroll
        for (int j = 0; j < 4; j++)
#pragma unroll
            for (int q = 0; q < 4; q++) acc[i][j][q] = 0.f;

    const int T = K >> 4;
    float4 sa[2], sb[2];
#pragma unroll
    for (int i = 0; i < 2; i++) {
        sa[i] = *(const float4*)&g.A[(size_t)(rowBase + aRow0 + i * 64) * K + aCol0];
        sb[i] = *(const float4*)&Bp[(size_t)(bRow0 + i * 8) * segN + colSeg + bCol0];
    }

    for (int t = 0; t < T; t++) {
        // stage with split
#pragma unroll
        for (int i = 0; i < 2; i++) {
            int r = aRow0 + i * 64;
            As2[aCol0 + 0][r] = split2(sa[i].x);
            As2[aCol0 + 1][r] = split2(sa[i].y);
            As2[aCol0 + 2][r] = split2(sa[i].z);
            As2[aCol0 + 3][r] = split2(sa[i].w);
            int br = bRow0 + i * 8;
            Bs2[br][bCol0 + 0] = split2(sb[i].x);
            Bs2[br][bCol0 + 1] = split2(sb[i].y);
            Bs2[br][bCol0 + 2] = split2(sb[i].z);
            Bs2[br][bCol0 + 3] = split2(sb[i].w);
        }
        __syncthreads();

        if (t + 1 < T) {
            int k0 = (t + 1) * 16;
#pragma unroll
            for (int i = 0; i < 2; i++) {
                sa[i] = *(const float4*)&g.A[(size_t)(rowBase + aRow0 + i * 64) * K + k0 + aCol0];
                sb[i] = *(const float4*)&Bp[(size_t)(k0 + bRow0 + i * 8) * segN + colSeg + bCol0];
            }
        }

#pragma unroll
        for (int kk = 0; kk < 16; kk += 8) {
            float2 bf[4][2];
#pragma unroll
            for (int nt = 0; nt < 4; nt++) {
                int n0 = wn * 32 + nt * 8 + lr;
                bf[nt][0] = Bs2[kk + lc][n0];
                bf[nt][1] = Bs2[kk + 4 + lc][n0];
            }
#pragma unroll
            for (int mt = 0; mt < 4; mt++) {
                int m0 = wm * 64 + mt * 16;
                float2 a0 = As2[kk + lc][m0 + lr];
                float2 a1 = As2[kk + lc][m0 + lr + 8];
                float2 a2 = As2[kk + 4 + lc][m0 + lr];
                float2 a3 = As2[kk + 4 + lc][m0 + lr + 8];
#pragma unroll
                for (int nt = 0; nt < 4; nt++) {
                    mma_tf32(acc[mt][nt], FU(a0.x), FU(a1.x), FU(a2.x), FU(a3.x),
                             FU(bf[nt][0].x), FU(bf[nt][1].x));
                    mma_tf32(acc[mt][nt], FU(a0.x), FU(a1.x), FU(a2.x), FU(a3.x),
                             FU(bf[nt][0].y), FU(bf[nt][1].y));
                    mma_tf32(acc[mt][nt], FU(a0.y), FU(a1.y), FU(a2.y), FU(a3.y),
                             FU(bf[nt][0].x), FU(bf[nt][1].x));
                }
            }
        }
        __syncthreads();
    }

#pragma unroll
    for (int mt = 0; mt < 4; mt++) {
#pragma unroll
        for (int nt = 0; nt < 4; nt++) {
            int col = colSeg + wn * 32 + nt * 8 + 2 * lc;
            float b0 = 0.f, b1 = 0.f;
            if (epi != 0) { b0 = bias[col]; b1 = bias[col + 1]; }
#pragma unroll
            for (int half = 0; half < 2; half++) {
                int row = rowBase + wm * 64 + mt * 16 + lr + half * 8;
                float v0 = acc[mt][nt][half * 2 + 0];
                float v1 = acc[mt][nt][half * 2 + 1];
                if (epi == 1) {
                    v0 = 1.f / (1.f + expf(-(v0 + b0)));
                    v1 = 1.f / (1.f + expf(-(v1 + b1)));
                } else if (epi == 2) {
                    v0 = fmaxf(v0 + b0, 0.f);
                    v1 = fmaxf(v1 + b1, 0.f);
                } else if (epi == 3) {
                    v0 += b0; v1 += b1;
                }
                float2 o; o.x = v0; o.y = v1;
                *(float2*)&Cp[(size_t)row * segN + col] = o;
            }
        }
    }
}

// ============================================================
// Tensor-core flash attention v2: K/V pre-split into interleaved
// float2 smem (stride 68 == 4 mod 16 -> frag LDS.64 conflict-free).
// Block 256 thr / 8 warps, q-tile 128. Dynamic smem 69632 B.
// ============================================================
#define ATT_STRIDE 68
#define ATT_HALF   (64 * ATT_STRIDE)
#define ATT_SMEM   (2 * ATT_HALF * 8)

extern __shared__ float2 att_sm[];

__global__ __launch_bounds__(256, 1) void attn_mma_kernel(
    const float* __restrict__ Q, const float* __restrict__ K,
    const float* __restrict__ V, float* __restrict__ O)
{
    float2* Ks2 = att_sm;               // Ks2[r*68 + c]
    float2* Vs2 = att_sm + ATT_HALF;

    const int tid = threadIdx.x;
    const int warp = tid >> 5;
    const int lane = tid & 31;
    const int g = lane >> 2;
    const int t = lane & 3;

    const int qb = blockIdx.x * 128;
    const int b = blockIdx.y >> 4, h = blockIdx.y & 15;
    const float* Qb = Q + (size_t)b * Nn * Dd + h * DhC;
    const float* Kb = K + (size_t)b * Nn * Dd + h * DhC;
    const float* Vb = V + (size_t)b * Nn * Dd + h * DhC;

    const int r0 = qb + warp * 16 + g;
    uint32_t qh[8][4];
    float    ql[8][4];
#pragma unroll
    for (int c = 0; c < 8; c++) {
        float v0 = Qb[(size_t)r0 * Dd + 8 * c + t] * 0.125f;
        float v1 = Qb[(size_t)(r0 + 8) * Dd + 8 * c + t] * 0.125f;
        float v2 = Qb[(size_t)r0 * Dd + 8 * c + t + 4] * 0.125f;
        float v3 = Qb[(size_t)(r0 + 8) * Dd + 8 * c + t + 4] * 0.125f;
        float h0 = tfhi(v0), h1 = tfhi(v1), h2 = tfhi(v2), h3 = tfhi(v3);
        qh[c][0] = FU(h0); ql[c][0] = v0 - h0;
        qh[c][1] = FU(h1); ql[c][1] = v1 - h1;
        qh[c][2] = FU(h2); ql[c][2] = v2 - h2;
        qh[c][3] = FU(h3); ql[c][3] = v3 - h3;
    }

    float m0 = -1e30f, m1 = -1e30f, l0 = 0.f, l1 = 0.f;
    float o[8][4];
#pragma unroll
    for (int j = 0; j < 8; j++)
#pragma unroll
        for (int q = 0; q < 4; q++) o[j][q] = 0.f;

    float4 kreg[4], vreg[4];
#pragma unroll
    for (int i = 0; i < 4; i++) {
        int f = tid + i * 256;
        int r = f >> 4, c4 = (f & 15) << 2;
        kreg[i] = *(const float4*)&Kb[(size_t)r * Dd + c4];
        vreg[i] = *(const float4*)&Vb[(size_t)r * Dd + c4];
    }

    const int src_lo = (lane & ~3) | (t >> 1);
    const int src_hi = src_lo + 2;
    const bool odd = (t & 1);

    for (int kt = 0; kt < 16; kt++) {
        __syncthreads();
#pragma unroll
        for (int i = 0; i < 4; i++) {
            int f = tid + i * 256;
            int r = f >> 4, c4 = (f & 15) << 2;
#pragma unroll
            for (int j = 0; j < 4; j++) {
                float kv = j == 0 ? kreg[i].x : j == 1 ? kreg[i].y : j == 2 ? kreg[i].z : kreg[i].w;
                float vv = j == 0 ? vreg[i].x : j == 1 ? vreg[i].y : j == 2 ? vreg[i].z : vreg[i].w;
                float kh = tfhi(kv), vh = tfhi(vv);
                Ks2[r * ATT_STRIDE + c4 + j] = make_float2(kh, kv - kh);
                Vs2[r * ATT_STRIDE + c4 + j] = make_float2(vh, vv - vh);
            }
        }
        __syncthreads();

        if (kt < 15) {
#pragma unroll
            for (int i = 0; i < 4; i++) {
                int f = tid + i * 256;
                int r = f >> 4, c4 = (f & 15) << 2;
                kreg[i] = *(const float4*)&Kb[(size_t)((kt + 1) * 64 + r) * Dd + c4];
                vreg[i] = *(const float4*)&Vb[(size_t)((kt + 1) * 64 + r) * Dd + c4];
            }
        }

        // ---- S = Q @ K^T ----
        float s[8][4];
#pragma unroll
        for (int j = 0; j < 8; j++)
#pragma unroll
            for (int q = 0; q < 4; q++) s[j][q] = 0.f;

#pragma unroll
        for (int c = 0; c < 8; c++) {
#pragma unroll
            for (int j = 0; j < 8; j++) {
                float2 b0p = Ks2[(8 * j + g) * ATT_STRIDE + 8 * c + t];
                float2 b1p = Ks2[(8 * j + g) * ATT_STRIDE + 8 * c + t + 4];
                mma_tf32(s[j], qh[c][0], qh[c][1], qh[c][2], qh[c][3], FU(b0p.x), FU(b1p.x));
                mma_tf32(s[j], qh[c][0], qh[c][1], qh[c][2], qh[c][3], FU(b0p.y), FU(b1p.y));
                mma_tf32(s[j], FU(ql[c][0]), FU(ql[c][1]), FU(ql[c][2]), FU(ql[c][3]),
                         FU(b0p.x), FU(b1p.x));
            }
        }

        // ---- online softmax ----
        float mx0 = -1e30f, mx1 = -1e30f;
#pragma unroll
        for (int j = 0; j < 8; j++) {
            mx0 = fmaxf(mx0, fmaxf(s[j][0], s[j][1]));
            mx1 = fmaxf(mx1, fmaxf(s[j][2], s[j][3]));
        }
        mx0 = fmaxf(mx0, __shfl_xor_sync(0xffffffffu, mx0, 1));
        mx0 = fmaxf(mx0, __shfl_xor_sync(0xffffffffu, mx0, 2));
        mx1 = fmaxf(mx1, __shfl_xor_sync(0xffffffffu, mx1, 1));
        mx1 = fmaxf(mx1, __shfl_xor_sync(0xffffffffu, mx1, 2));
        float mn0 = fmaxf(m0, mx0), mn1 = fmaxf(m1, mx1);
        float al0 = __expf(m0 - mn0), al1 = __expf(m1 - mn1);
        m0 = mn0; m1 = mn1;
        float rs0 = 0.f, rs1 = 0.f;
#pragma unroll
        for (int j = 0; j < 8; j++) {
            s[j][0] = __expf(s[j][0] - mn0); rs0 += s[j][0];
            s[j][1] = __expf(s[j][1] - mn0); rs0 += s[j][1];
            s[j][2] = __expf(s[j][2] - mn1); rs1 += s[j][2];
            s[j][3] = __expf(s[j][3] - mn1); rs1 += s[j][3];
        }
        l0 = l0 * al0 + rs0;
        l1 = l1 * al1 + rs1;
#pragma unroll
        for (int j = 0; j < 8; j++) {
            o[j][0] *= al0; o[j][1] *= al0; o[j][2] *= al1; o[j][3] *= al1;
        }

        // ---- O += P @ V ----
#pragma unroll
        for (int c = 0; c < 8; c++) {
            float e00 = __shfl_sync(0xffffffffu, s[c][0], src_lo);
            float e01 = __shfl_sync(0xffffffffu, s[c][1], src_lo);
            float e20 = __shfl_sync(0xffffffffu, s[c][2], src_lo);
            float e21 = __shfl_sync(0xffffffffu, s[c][3], src_lo);
            float f00 = __shfl_sync(0xffffffffu, s[c][0], src_hi);
            float f01 = __shfl_sync(0xffffffffu, s[c][1], src_hi);
            float f20 = __shfl_sync(0xffffffffu, s[c][2], src_hi);
            float f21 = __shfl_sync(0xffffffffu, s[c][3], src_hi);
            float a0 = odd ? e01 : e00;
            float a1 = odd ? e21 : e20;
            float a2 = odd ? f01 : f00;
            float a3 = odd ? f21 : f20;
            float ah0 = tfhi(a0), ah1 = tfhi(a1), ah2 = tfhi(a2), ah3 = tfhi(a3);
            uint32_t uah0 = FU(ah0), uah1 = FU(ah1), uah2 = FU(ah2), uah3 = FU(ah3);
            uint32_t ual0 = FU(a0 - ah0), ual1 = FU(a1 - ah1);
            uint32_t ual2 = FU(a2 - ah2), ual3 = FU(a3 - ah3);
#pragma unroll
            for (int j = 0; j < 8; j++) {
                float2 v0p = Vs2[(8 * c + t) * ATT_STRIDE + 8 * j + g];
                float2 v1p = Vs2[(8 * c + t + 4) * ATT_STRIDE + 8 * j + g];
                mma_tf32(o[j], uah0, uah1, uah2, uah3, FU(v0p.x), FU(v1p.x));
                mma_tf32(o[j], uah0, uah1, uah2, uah3, FU(v0p.y), FU(v1p.y));
                mma_tf32(o[j], ual0, ual1, ual2, ual3, FU(v0p.x), FU(v1p.x));
            }
        }
    }

    l0 += __shfl_xor_sync(0xffffffffu, l0, 1);
    l0 += __shfl_xor_sync(0xffffffffu, l0, 2);
    l1 += __shfl_xor_sync(0xffffffffu, l1, 1);
    l1 += __shfl_xor_sync(0xffffffffu, l1, 2);
    float inv0 = 1.f / l0, inv1 = 1.f / l1;
#pragma unroll
    for (int j = 0; j < 8; j++) {
        int col = h * DhC + 8 * j + 2 * t;
        float2 w0; w0.x = o[j][0] * inv0; w0.y = o[j][1] * inv0;
        float2 w1; w1.x = o[j][2] * inv1; w1.y = o[j][3] * inv1;
        *(float2*)&O[(size_t)(b * Nn + r0) * Dd + col] = w0;
        *(float2*)&O[(size_t)(b * Nn + r0 + 8) * Dd + col] = w1;
    }
}

// ============================================================
// Splat influence v2: 4 tokens per block (4x less splat re-read).
// grid (Nn/4, B), 256 threads.
// ============================================================
__global__ __launch_bounds__(256) void infl_kernel(
    const float* __restrict__ x, const float* __restrict__ sp,
    const float* __restrict__ sscale, const float* __restrict__ simp,
    float* __restrict__ infl)
{
    __shared__ float xs[4][Dd];
    __shared__ float xred[8][4];
    __shared__ float x2s[4];
    const int n0 = blockIdx.x * 4, b = blockIdx.y;
    const int tid = threadIdx.x;
    const int lane = tid & 31, w = tid >> 5;

    float p2[4] = {0.f, 0.f, 0.f, 0.f};
#pragma unroll
    for (int i = 0; i < 16; i++) {
        int idx = tid + i * 256;
        int tok = idx >> 10, d = idx & 1023;
        float v = x[(size_t)(b * Nn + n0 + tok) * Dd + d];
        xs[tok][d] = v;
        p2[tok] += v * v;
    }
#pragma unroll
    for (int tok = 0; tok < 4; tok++) {
        float v = p2[tok];
#pragma unroll
        for (int off = 16; off; off >>= 1) v += __shfl_xor_sync(0xffffffffu, v, off);
        if (lane == 0) xred[w][tok] = v;
    }
    __syncthreads();
    if (tid < 4) {
        float v = 0.f;
#pragma unroll
        for (int i = 0; i < 8; i++) v += xred[i][tid];
        x2s[tid] = v;
    }
    __syncthreads();

    for (int p = 0; p < 8; p++) {
        int s = w + 8 * p;
        const float* spr = &sp[(size_t)s * Dd];
        float dot0 = 0.f, dot1 = 0.f, dot2 = 0.f, dot3 = 0.f, s2 = 0.f;
        for (int d = lane; d < Dd; d += 32) {
            float pv = spr[d];
            s2 += pv * pv;
            dot0 += xs[0][d] * pv;
            dot1 += xs[1][d] * pv;
            dot2 += xs[2][d] * pv;
            dot3 += xs[3][d] * pv;
        }
#pragma unroll
        for (int off = 16; off; off >>= 1) {
            dot0 += __shfl_xor_sync(0xffffffffu, dot0, off);
            dot1 += __shfl_xor_sync(0xffffffffu, dot1, off);
            dot2 += __shfl_xor_sync(0xffffffffu, dot2, off);
            dot3 += __shfl_xor_sync(0xffffffffu, dot3, off);
            s2   += __shfl_xor_sync(0xffffffffu, s2, off);
        }
        if (lane == 0) {
            float sc = fmaxf(fabsf(sscale[s]), 1e-6f);
            float inv = -0.5f / (sc * sc);
            float imp = fabsf(simp[s]);
            float d20 = fmaxf(x2s[0] + s2 - 2.f * dot0, 0.f);
            float d21 = fmaxf(x2s[1] + s2 - 2.f * dot1, 0.f);
            float d22 = fmaxf(x2s[2] + s2 - 2.f * dot2, 0.f);
            float d23 = fmaxf(x2s[3] + s2 - 2.f * dot3, 0.f);
            infl[(size_t)(b * Nn + n0 + 0) * Ss + s] = expf(d20 * inv) * imp;
            infl[(size_t)(b * Nn + n0 + 1) * Ss + s] = expf(d21 * inv) * imp;
            infl[(size_t)(b * Nn + n0 + 2) * Ss + s] = expf(d22 * inv) * imp;
            infl[(size_t)(b * Nn + n0 + 3) * Ss + s] = expf(d23 * inv) * imp;
        }
    }
}

// total[b,s] = max(sum_n infl, 1e-8)
__global__ __launch_bounds__(256) void total_kernel(
    const float* __restrict__ infl, float* __restrict__ total)
{
    __shared__ float red[8];
    int s = blockIdx.x, b = blockIdx.y, tid = threadIdx.x;
    float acc = 0.f;
    for (int n = tid; n < Nn; n += 256) acc += infl[(size_t)(b * Nn + n) * Ss + s];
#pragma unroll
    for (int off = 16; off; off >>= 1) acc += __shfl_xor_sync(0xffffffffu, acc, off);
    if ((tid & 31) == 0) red[tid >> 5] = acc;
    __syncthreads();
    if (tid == 0) {
        float t = 0.f;
#pragma unroll
        for (int i = 0; i < 8; i++) t += red[i];
        total[b * Ss + s] = fmaxf(t, 1e-8f);
    }
}

__global__ __launch_bounds__(256) void gather_kernel(
    const float* __restrict__ x, const float* __restrict__ infl,
    const float* __restrict__ total, float* __restrict__ gath)
{
    int s = blockIdx.x, b = blockIdx.y, tid = threadIdx.x;
    float acc[4] = {0.f, 0.f, 0.f, 0.f};
    for (int n = 0; n < Nn; n++) {
        float wv = __ldg(&infl[(size_t)(b * Nn + n) * Ss + s]);
        if (wv != 0.f) {
            const float* xr = &x[(size_t)(b * Nn + n) * Dd];
#pragma unroll
            for (int i = 0; i < 4; i++) acc[i] += wv * xr[tid + 256 * i];
        }
    }
    float inv = 1.f / total[b * Ss + s];
#pragma unroll
    for (int i = 0; i < 4; i++)
        gath[(size_t)(b * Ss + s) * Dd + tid + 256 * i] = acc[i] * inv;
}

__global__ __launch_bounds__(128) void trans_kernel(
    const float* __restrict__ enc, const float* __restrict__ Wt,
    const float* __restrict__ bt, float* __restrict__ trans)
{
    int s = blockIdx.x;
    int e = blockIdx.y * 128 + threadIdx.x;
    const float* wp = &Wt[(size_t)s * DbC * DbC];
    const float* e0 = &enc[(size_t)(0 * Ss + s) * DbC];
    const float* e1 = &enc[(size_t)(1 * Ss + s) * DbC];
    float a0 = 0.f, a1 = 0.f;
    for (int d = 0; d < DbC; d++) {
        float wv = wp[(size_t)d * DbC + e];
        a0 += e0[d] * wv;
        a1 += e1[d] * wv;
    }
    float bv = bt[s * DbC + e];
    trans[(size_t)(0 * Ss + s) * DbC + e] = a0 + bv;
    trans[(size_t)(1 * Ss + s) * DbC + e] = a1 + bv;
}

// blend v2: 8 tokens/block; block-uniform zero-skip on dec reads.
// grid (Nn/8, B), 256 threads.
__global__ __launch_bounds__(256) void flow_blend_kernel(
    const float* __restrict__ infl, const float* __restrict__ dec,
    const float* __restrict__ gate, const float* __restrict__ stdo,
    float* __restrict__ blend)
{
    __shared__ float is[8][Ss];
    const int n0 = blockIdx.x * 8, b = blockIdx.y, tid = threadIdx.x;
    for (int i = tid; i < 8 * Ss; i += 256)
        is[i >> 6][i & 63] = infl[(size_t)(b * Nn + n0 + (i >> 6)) * Ss + (i & 63)];
    __syncthreads();

    float acc[8][4];
#pragma unroll
    for (int tk = 0; tk < 8; tk++)
#pragma unroll
        for (int i = 0; i < 4; i++) acc[tk][i] = 0.f;

    for (int s = 0; s < Ss; s++) {
        float w0 = is[0][s], w1 = is[1][s], w2 = is[2][s], w3 = is[3][s];
        float w4 = is[4][s], w5 = is[5][s], w6 = is[6][s], w7 = is[7][s];
        // block-uniform predicate (is[] identical across threads)
        if ((w0 != 0.f) | (w1 != 0.f) | (w2 != 0.f) | (w3 != 0.f) |
            (w4 != 0.f) | (w5 != 0.f) | (w6 != 0.f) | (w7 != 0.f)) {
            const float* dr = &dec[(size_t)(b * Ss + s) * Dd];
#pragma unroll
            for (int i = 0; i < 4; i++) {
                float dv = dr[tid + 256 * i];
                acc[0][i] += w0 * dv; acc[1][i] += w1 * dv;
                acc[2][i] += w2 * dv; acc[3][i] += w3 * dv;
                acc[4][i] += w4 * dv; acc[5][i] += w5 * dv;
                acc[6][i] += w6 * dv; acc[7][i] += w7 * dv;
            }
        }
    }

#pragma unroll
    for (int tk = 0; tk < 8; tk++) {
#pragma unroll
        for (int i = 0; i < 4; i++) {
            size_t idx = (size_t)(b * Nn + n0 + tk) * Dd + tid + 256 * i;
            blend[idx] = 0.6f * stdo[idx] + 0.4f * acc[tk][i] * gate[idx];
        }
    }
}

// ============================================================
extern "C" void kernel_launch(void* const* d_in, const int* in_sizes, int n_in,
                              void* d_out, int out_size)
{
    const float* x    = (const float*)d_in[0];
    const float* Wq   = (const float*)d_in[1];
    const float* Wk   = (const float*)d_in[2];
    const float* Wv   = (const float*)d_in[3];
    const float* Wo   = (const float*)d_in[4];
    const float* sp   = (const float*)d_in[5];
    const float* ssc  = (const float*)d_in[6];
    const float* simp = (const float*)d_in[7];
    const float* We   = (const float*)d_in[8];
    const float* be   = (const float*)d_in[9];
    const float* Wt   = (const float*)d_in[10];
    const float* bt   = (const float*)d_in[11];
    const float* Wd   = (const float*)d_in[12];
    const float* bd   = (const float*)d_in[13];
    const float* Wg   = (const float*)d_in[14];
    const float* bg   = (const float*)d_in[15];

    float *Qp, *Kp, *Vp, *Gp, *Stdp, *Inflp, *Totp, *Gathp, *Encp, *Transp, *Decp, *Blendp;
    cudaGetSymbolAddress((void**)&Qp, g_Q);
    cudaGetSymbolAddress((void**)&Kp, g_K);
    cudaGetSymbolAddress((void**)&Vp, g_V);
    cudaGetSymbolAddress((void**)&Gp, g_G);
    cudaGetSymbolAddress((void**)&Stdp, g_std);
    cudaGetSymbolAddress((void**)&Inflp, g_infl);
    cudaGetSymbolAddress((void**)&Totp, g_total);
    cudaGetSymbolAddress((void**)&Gathp, g_gath);
    cudaGetSymbolAddress((void**)&Encp, g_enc);
    cudaGetSymbolAddress((void**)&Transp, g_trans);
    cudaGetSymbolAddress((void**)&Decp, g_dec);
    cudaGetSymbolAddress((void**)&Blendp, g_blend);

    cudaFuncSetAttribute(attn_mma_kernel, cudaFuncAttributeMaxDynamicSharedMemorySize, ATT_SMEM);

    const int M = Bb * Nn;   // 2048

    // ---- fused Q/K/V/Gate projection ----
    {
        GArgs a;
        a.A = x; a.K = Dd; a.segN = Dd;
        a.B[0] = Wq; a.B[1] = Wk; a.B[2] = Wv; a.B[3] = Wg;
        a.bias[0] = nullptr; a.bias[1] = nullptr; a.bias[2] = nullptr; a.bias[3] = bg;
        a.C[0] = Qp; a.C[1] = Kp; a.C[2] = Vp; a.C[3] = Gp;
        a.epi[0] = 0; a.epi[1] = 0; a.epi[2] = 0; a.epi[3] = 1;
        tf32_gemm<<<dim3(32, M / 128), 256>>>(a);
    }

    attn_mma_kernel<<<dim3(Nn / 128, Bb * Hh), 256, ATT_SMEM>>>(Qp, Kp, Vp, Stdp);

    infl_kernel<<<dim3(Nn / 4, Bb), 256>>>(x, sp, ssc, simp, Inflp);
    total_kernel<<<dim3(Ss, Bb), 256>>>(Inflp, Totp);
    gather_kernel<<<dim3(Ss, Bb), 256>>>(x, Inflp, Totp, Gathp);

    {
        GArgs a;
        a.A = Gathp; a.K = Dd; a.segN = DbC;
        for (int i = 0; i < 4; i++) { a.B[i] = We; a.bias[i] = be; a.C[i] = Encp; a.epi[i] = 2; }
        tf32_gemm<<<dim3(DbC / 128, 1), 256>>>(a);
    }

    trans_kernel<<<dim3(Ss, DbC / 128), 128>>>(Encp, Wt, bt, Transp);

    {
        GArgs a;
        a.A = Transp; a.K = DbC; a.segN = Dd;
        for (int i = 0; i < 4; i++) { a.B[i] = Wd; a.bias[i] = bd; a.C[i] = Decp; a.epi[i] = 3; }
        tf32_gemm<<<dim3(Dd / 128, 1), 256>>>(a);
    }

    flow_blend_kernel<<<dim3(Nn / 8, Bb), 256>>>(Inflp, Decp, Gp, Stdp, Blendp);

    {
        GArgs a;
        a.A = Blendp; a.K = Dd; a.segN = Dd;
        for (int i = 0; i < 4; i++) { a.B[i] = Wo; a.bias[i] = nullptr; a.C[i] = (float*)d_out; a.epi[i] = 0; }
        tf32_gemm<<<dim3(Dd / 128, M / 128), 256>>>(a);
    }
}

// round 7
// speedup vs baseline: 1.4070x; 1.4070x over previous
#include <cuda_runtime.h>
#include <cstdint>

#define Bb 2
#define Nn 1024
#define Dd 1024
#define Hh 16
#define DhC 64
#define Ss 64
#define DbC 512

// -------- scratch (static device globals) --------
__device__ float g_Q[Bb*Nn*Dd];
__device__ float g_K[Bb*Nn*Dd];
__device__ float g_V[Bb*Nn*Dd];
__device__ float g_G[Bb*Nn*Dd];
__device__ float g_std[Bb*Nn*Dd];
__device__ float g_infl[Bb*Nn*Ss];
__device__ float g_total[Bb*Ss];
__device__ float g_gath[Bb*Ss*Dd];
__device__ float g_enc[Bb*Ss*DbC];
__device__ float g_trans[Bb*Ss*DbC];
__device__ float g_dec[Bb*Ss*Dd];
__device__ float g_blend[Bb*Nn*Dd];

__device__ __forceinline__ uint32_t f2tf32(float x) {
    uint32_t r;
    asm("cvt.rna.tf32.f32 %0, %1;" : "=r"(r) : "f"(x));
    return r;
}
__device__ __forceinline__ float tfhi(float x) {
    return __uint_as_float(__float_as_uint(x) & 0xFFFFE000u);
}
__device__ __forceinline__ void mma_tf32(float* c,
    uint32_t a0, uint32_t a1, uint32_t a2, uint32_t a3,
    uint32_t b0, uint32_t b1)
{
    asm volatile(
        "mma.sync.aligned.m16n8k8.row.col.f32.tf32.tf32.f32 "
        "{%0,%1,%2,%3},{%4,%5,%6,%7},{%8,%9},{%0,%1,%2,%3};"
        : "+f"(c[0]), "+f"(c[1]), "+f"(c[2]), "+f"(c[3])
        : "r"(a0), "r"(a1), "r"(a2), "r"(a3), "r"(b0), "r"(b1));
}
#define FU(x) __float_as_uint(x)

// ============================================================
// tf32 mma.sync GEMM (exact R4 version — 909us baseline)
// ============================================================
struct GArgs {
    const float* A;
    const float* B[4];
    const float* bias[4];
    float*       C[4];
    int K;
    int segN;
    int epi[4];
};

#define SPAD 140

__global__ __launch_bounds__(256, 2) void tf32_gemm(GArgs g)
{
    __shared__ float As[16][SPAD];
    __shared__ float Bs[16][SPAD];

    const int tid = threadIdx.x;
    const int warp = tid >> 5;
    const int lane = tid & 31;
    const int lr = lane >> 2;
    const int lc = lane & 3;
    const int wm = warp >> 2;
    const int wn = warp & 3;

    const int seg    = (blockIdx.x * 128) / g.segN;
    const int colSeg = (blockIdx.x * 128) % g.segN;
    const int rowBase = blockIdx.y * 128;
    const float* __restrict__ Bp   = g.B[seg];
    const float* __restrict__ bias = g.bias[seg];
    float* __restrict__ Cp         = g.C[seg];
    const int epi  = g.epi[seg];
    const int K    = g.K;
    const int segN = g.segN;

    const int aRow0 = tid >> 2;
    const int aCol0 = (tid & 3) << 2;
    const int bRow0 = tid >> 5;
    const int bCol0 = (tid & 31) << 2;

    float acc[4][4][4];
#pragma unroll
    for (int i = 0; i < 4; i++)
#pragma unroll
        for (int j = 0; j < 4; j++)
#pragma unroll
            for (int q = 0; q < 4; q++) acc[i][j][q] = 0.f;

    const int T = K >> 4;
    float4 sa[2], sb[2];
#pragma unroll
    for (int i = 0; i < 2; i++) {
        sa[i] = *(const float4*)&g.A[(size_t)(rowBase + aRow0 + i * 64) * K + aCol0];
        sb[i] = *(const float4*)&Bp[(size_t)(bRow0 + i * 8) * segN + colSeg + bCol0];
    }

    for (int t = 0; t < T; t++) {
#pragma unroll
        for (int i = 0; i < 2; i++) {
            int r = aRow0 + i * 64;
            As[aCol0 + 0][r] = sa[i].x;
            As[aCol0 + 1][r] = sa[i].y;
            As[aCol0 + 2][r] = sa[i].z;
            As[aCol0 + 3][r] = sa[i].w;
            *(float4*)&Bs[bRow0 + i * 8][bCol0] = sb[i];
        }
        __syncthreads();

        if (t + 1 < T) {
            int k0 = (t + 1) * 16;
#pragma unroll
            for (int i = 0; i < 2; i++) {
                sa[i] = *(const float4*)&g.A[(size_t)(rowBase + aRow0 + i * 64) * K + k0 + aCol0];
                sb[i] = *(const float4*)&Bp[(size_t)(k0 + bRow0 + i * 8) * segN + colSeg + bCol0];
            }
        }

#pragma unroll
        for (int kk = 0; kk < 16; kk += 8) {
            uint32_t bh[4][2], bl[4][2];
#pragma unroll
            for (int nt = 0; nt < 4; nt++) {
                int n0 = wn * 32 + nt * 8 + lr;
                float b0 = Bs[kk + lc][n0];
                float b1 = Bs[kk + 4 + lc][n0];
                bh[nt][0] = f2tf32(b0);
                bl[nt][0] = f2tf32(b0 - __uint_as_float(bh[nt][0]));
                bh[nt][1] = f2tf32(b1);
                bl[nt][1] = f2tf32(b1 - __uint_as_float(bh[nt][1]));
            }
#pragma unroll
            for (int mt = 0; mt < 4; mt++) {
                int m0 = wm * 64 + mt * 16;
                float a0 = As[kk + lc][m0 + lr];
                float a1 = As[kk + lc][m0 + lr + 8];
                float a2 = As[kk + 4 + lc][m0 + lr];
                float a3 = As[kk + 4 + lc][m0 + lr + 8];
                uint32_t ah0 = f2tf32(a0), ah1 = f2tf32(a1), ah2 = f2tf32(a2), ah3 = f2tf32(a3);
                uint32_t al0 = f2tf32(a0 - __uint_as_float(ah0));
                uint32_t al1 = f2tf32(a1 - __uint_as_float(ah1));
                uint32_t al2 = f2tf32(a2 - __uint_as_float(ah2));
                uint32_t al3 = f2tf32(a3 - __uint_as_float(ah3));
#pragma unroll
                for (int nt = 0; nt < 4; nt++) {
                    mma_tf32(acc[mt][nt], ah0, ah1, ah2, ah3, bh[nt][0], bh[nt][1]);
                    mma_tf32(acc[mt][nt], ah0, ah1, ah2, ah3, bl[nt][0], bl[nt][1]);
                    mma_tf32(acc[mt][nt], al0, al1, al2, al3, bh[nt][0], bh[nt][1]);
                }
            }
        }
        __syncthreads();
    }

#pragma unroll
    for (int mt = 0; mt < 4; mt++) {
#pragma unroll
        for (int nt = 0; nt < 4; nt++) {
            int col = colSeg + wn * 32 + nt * 8 + 2 * lc;
            float b0 = 0.f, b1 = 0.f;
            if (epi != 0) { b0 = bias[col]; b1 = bias[col + 1]; }
#pragma unroll
            for (int half = 0; half < 2; half++) {
                int row = rowBase + wm * 64 + mt * 16 + lr + half * 8;
                float v0 = acc[mt][nt][half * 2 + 0];
                float v1 = acc[mt][nt][half * 2 + 1];
                if (epi == 1) {
                    v0 = 1.f / (1.f + expf(-(v0 + b0)));
                    v1 = 1.f / (1.f + expf(-(v1 + b1)));
                } else if (epi == 2) {
                    v0 = fmaxf(v0 + b0, 0.f);
                    v1 = fmaxf(v1 + b1, 0.f);
                } else if (epi == 3) {
                    v0 += b0; v1 += b1;
                }
                float2 o; o.x = v0; o.y = v1;
                *(float2*)&Cp[(size_t)row * segN + col] = o;
            }
        }
    }
}

// ============================================================
// Tensor-core flash attention (exact R4 version)
// ============================================================
__global__ __launch_bounds__(256, 1) void attn_mma_kernel(
    const float* __restrict__ Q, const float* __restrict__ K,
    const float* __restrict__ V, float* __restrict__ O)
{
    __shared__ float Ks[64][68];
    __shared__ float Vs[64][72];

    const int tid = threadIdx.x;
    const int warp = tid >> 5;
    const int lane = tid & 31;
    const int g = lane >> 2;
    const int t = lane & 3;

    const int qb = blockIdx.x * 128;
    const int b = blockIdx.y >> 4, h = blockIdx.y & 15;
    const float* Qb = Q + (size_t)b * Nn * Dd + h * DhC;
    const float* Kb = K + (size_t)b * Nn * Dd + h * DhC;
    const float* Vb = V + (size_t)b * Nn * Dd + h * DhC;

    const int r0 = qb + warp * 16 + g;
    uint32_t qh[8][4];
    float    ql[8][4];
#pragma unroll
    for (int c = 0; c < 8; c++) {
        float v0 = Qb[(size_t)r0 * Dd + 8 * c + t] * 0.125f;
        float v1 = Qb[(size_t)(r0 + 8) * Dd + 8 * c + t] * 0.125f;
        float v2 = Qb[(size_t)r0 * Dd + 8 * c + t + 4] * 0.125f;
        float v3 = Qb[(size_t)(r0 + 8) * Dd + 8 * c + t + 4] * 0.125f;
        float h0 = tfhi(v0), h1 = tfhi(v1), h2 = tfhi(v2), h3 = tfhi(v3);
        qh[c][0] = FU(h0); ql[c][0] = v0 - h0;
        qh[c][1] = FU(h1); ql[c][1] = v1 - h1;
        qh[c][2] = FU(h2); ql[c][2] = v2 - h2;
        qh[c][3] = FU(h3); ql[c][3] = v3 - h3;
    }

    float m0 = -1e30f, m1 = -1e30f, l0 = 0.f, l1 = 0.f;
    float o[8][4];
#pragma unroll
    for (int j = 0; j < 8; j++)
#pragma unroll
        for (int q = 0; q < 4; q++) o[j][q] = 0.f;

    float4 kreg[4], vreg[4];
#pragma unroll
    for (int i = 0; i < 4; i++) {
        int f = tid + i * 256;
        int r = f >> 4, c4 = (f & 15) << 2;
        kreg[i] = *(const float4*)&Kb[(size_t)r * Dd + c4];
        vreg[i] = *(const float4*)&Vb[(size_t)r * Dd + c4];
    }

    const int src_lo = (lane & ~3) | (t >> 1);
    const int src_hi = src_lo + 2;
    const bool odd = (t & 1);

    for (int kt = 0; kt < 16; kt++) {
        __syncthreads();
#pragma unroll
        for (int i = 0; i < 4; i++) {
            int f = tid + i * 256;
            int r = f >> 4, c4 = (f & 15) << 2;
            *(float4*)&Ks[r][c4] = kreg[i];
            *(float4*)&Vs[r][c4] = vreg[i];
        }
        __syncthreads();

        if (kt < 15) {
#pragma unroll
            for (int i = 0; i < 4; i++) {
                int f = tid + i * 256;
                int r = f >> 4, c4 = (f & 15) << 2;
                kreg[i] = *(const float4*)&Kb[(size_t)((kt + 1) * 64 + r) * Dd + c4];
                vreg[i] = *(const float4*)&Vb[(size_t)((kt + 1) * 64 + r) * Dd + c4];
            }
        }

        float s[8][4];
#pragma unroll
        for (int j = 0; j < 8; j++)
#pragma unroll
            for (int q = 0; q < 4; q++) s[j][q] = 0.f;

#pragma unroll
        for (int c = 0; c < 8; c++) {
#pragma unroll
            for (int j = 0; j < 8; j++) {
                float b0 = Ks[8 * j + g][8 * c + t];
                float b1 = Ks[8 * j + g][8 * c + t + 4];
                float bh0 = tfhi(b0), bh1 = tfhi(b1);
                uint32_t ubh0 = FU(bh0), ubh1 = FU(bh1);
                uint32_t ubl0 = FU(b0 - bh0), ubl1 = FU(b1 - bh1);
                mma_tf32(s[j], qh[c][0], qh[c][1], qh[c][2], qh[c][3], ubh0, ubh1);
                mma_tf32(s[j], qh[c][0], qh[c][1], qh[c][2], qh[c][3], ubl0, ubl1);
                mma_tf32(s[j], FU(ql[c][0]), FU(ql[c][1]), FU(ql[c][2]), FU(ql[c][3]), ubh0, ubh1);
            }
        }

        float mx0 = -1e30f, mx1 = -1e30f;
#pragma unroll
        for (int j = 0; j < 8; j++) {
            mx0 = fmaxf(mx0, fmaxf(s[j][0], s[j][1]));
            mx1 = fmaxf(mx1, fmaxf(s[j][2], s[j][3]));
        }
        mx0 = fmaxf(mx0, __shfl_xor_sync(0xffffffffu, mx0, 1));
        mx0 = fmaxf(mx0, __shfl_xor_sync(0xffffffffu, mx0, 2));
        mx1 = fmaxf(mx1, __shfl_xor_sync(0xffffffffu, mx1, 1));
        mx1 = fmaxf(mx1, __shfl_xor_sync(0xffffffffu, mx1, 2));
        float mn0 = fmaxf(m0, mx0), mn1 = fmaxf(m1, mx1);
        float al0 = __expf(m0 - mn0), al1 = __expf(m1 - mn1);
        m0 = mn0; m1 = mn1;
        float rs0 = 0.f, rs1 = 0.f;
#pragma unroll
        for (int j = 0; j < 8; j++) {
            s[j][0] = __expf(s[j][0] - mn0); rs0 += s[j][0];
            s[j][1] = __expf(s[j][1] - mn0); rs0 += s[j][1];
            s[j][2] = __expf(s[j][2] - mn1); rs1 += s[j][2];
            s[j][3] = __expf(s[j][3] - mn1); rs1 += s[j][3];
        }
        l0 = l0 * al0 + rs0;
        l1 = l1 * al1 + rs1;
#pragma unroll
        for (int j = 0; j < 8; j++) {
            o[j][0] *= al0; o[j][1] *= al0; o[j][2] *= al1; o[j][3] *= al1;
        }

#pragma unroll
        for (int c = 0; c < 8; c++) {
            float e00 = __shfl_sync(0xffffffffu, s[c][0], src_lo);
            float e01 = __shfl_sync(0xffffffffu, s[c][1], src_lo);
            float e20 = __shfl_sync(0xffffffffu, s[c][2], src_lo);
            float e21 = __shfl_sync(0xffffffffu, s[c][3], src_lo);
            float f00 = __shfl_sync(0xffffffffu, s[c][0], src_hi);
            float f01 = __shfl_sync(0xffffffffu, s[c][1], src_hi);
            float f20 = __shfl_sync(0xffffffffu, s[c][2], src_hi);
            float f21 = __shfl_sync(0xffffffffu, s[c][3], src_hi);
            float a0 = odd ? e01 : e00;
            float a1 = odd ? e21 : e20;
            float a2 = odd ? f01 : f00;
            float a3 = odd ? f21 : f20;
            float ah0 = tfhi(a0), ah1 = tfhi(a1), ah2 = tfhi(a2), ah3 = tfhi(a3);
            uint32_t uah0 = FU(ah0), uah1 = FU(ah1), uah2 = FU(ah2), uah3 = FU(ah3);
            uint32_t ual0 = FU(a0 - ah0), ual1 = FU(a1 - ah1);
            uint32_t ual2 = FU(a2 - ah2), ual3 = FU(a3 - ah3);
#pragma unroll
            for (int j = 0; j < 8; j++) {
                float b0 = Vs[8 * c + t][8 * j + g];
                float b1 = Vs[8 * c + t + 4][8 * j + g];
                float bh0 = tfhi(b0), bh1 = tfhi(b1);
                uint32_t ubh0 = FU(bh0), ubh1 = FU(bh1);
                uint32_t ubl0 = FU(b0 - bh0), ubl1 = FU(b1 - bh1);
                mma_tf32(o[j], uah0, uah1, uah2, uah3, ubh0, ubh1);
                mma_tf32(o[j], uah0, uah1, uah2, uah3, ubl0, ubl1);
                mma_tf32(o[j], ual0, ual1, ual2, ual3, ubh0, ubh1);
            }
        }
    }

    l0 += __shfl_xor_sync(0xffffffffu, l0, 1);
    l0 += __shfl_xor_sync(0xffffffffu, l0, 2);
    l1 += __shfl_xor_sync(0xffffffffu, l1, 1);
    l1 += __shfl_xor_sync(0xffffffffu, l1, 2);
    float inv0 = 1.f / l0, inv1 = 1.f / l1;
#pragma unroll
    for (int j = 0; j < 8; j++) {
        int col = h * DhC + 8 * j + 2 * t;
        float2 w0; w0.x = o[j][0] * inv0; w0.y = o[j][1] * inv0;
        float2 w1; w1.x = o[j][2] * inv1; w1.y = o[j][3] * inv1;
        *(float2*)&O[(size_t)(b * Nn + r0) * Dd + col] = w0;
        *(float2*)&O[(size_t)(b * Nn + r0 + 8) * Dd + col] = w1;
    }
}

// ============================================================
// Splat influence: 4 tokens per block (R6 version — L2 traffic /4)
// ============================================================
__global__ __launch_bounds__(256) void infl_kernel(
    const float* __restrict__ x, const float* __restrict__ sp,
    const float* __restrict__ sscale, const float* __restrict__ simp,
    float* __restrict__ infl)
{
    __shared__ float xs[4][Dd];
    __shared__ float xred[8][4];
    __shared__ float x2s[4];
    const int n0 = blockIdx.x * 4, b = blockIdx.y;
    const int tid = threadIdx.x;
    const int lane = tid & 31, w = tid >> 5;

    float p2[4] = {0.f, 0.f, 0.f, 0.f};
#pragma unroll
    for (int i = 0; i < 16; i++) {
        int idx = tid + i * 256;
        int tok = idx >> 10, d = idx & 1023;
        float v = x[(size_t)(b * Nn + n0 + tok) * Dd + d];
        xs[tok][d] = v;
        p2[tok] += v * v;
    }
#pragma unroll
    for (int tok = 0; tok < 4; tok++) {
        float v = p2[tok];
#pragma unroll
        for (int off = 16; off; off >>= 1) v += __shfl_xor_sync(0xffffffffu, v, off);
        if (lane == 0) xred[w][tok] = v;
    }
    __syncthreads();
    if (tid < 4) {
        float v = 0.f;
#pragma unroll
        for (int i = 0; i < 8; i++) v += xred[i][tid];
        x2s[tid] = v;
    }
    __syncthreads();

    for (int p = 0; p < 8; p++) {
        int s = w + 8 * p;
        const float* spr = &sp[(size_t)s * Dd];
        float dot0 = 0.f, dot1 = 0.f, dot2 = 0.f, dot3 = 0.f, s2 = 0.f;
        for (int d = lane; d < Dd; d += 32) {
            float pv = spr[d];
            s2 += pv * pv;
            dot0 += xs[0][d] * pv;
            dot1 += xs[1][d] * pv;
            dot2 += xs[2][d] * pv;
            dot3 += xs[3][d] * pv;
        }
#pragma unroll
        for (int off = 16; off; off >>= 1) {
            dot0 += __shfl_xor_sync(0xffffffffu, dot0, off);
            dot1 += __shfl_xor_sync(0xffffffffu, dot1, off);
            dot2 += __shfl_xor_sync(0xffffffffu, dot2, off);
            dot3 += __shfl_xor_sync(0xffffffffu, dot3, off);
            s2   += __shfl_xor_sync(0xffffffffu, s2, off);
        }
        if (lane == 0) {
            float sc = fmaxf(fabsf(sscale[s]), 1e-6f);
            float inv = -0.5f / (sc * sc);
            float imp = fabsf(simp[s]);
            float d20 = fmaxf(x2s[0] + s2 - 2.f * dot0, 0.f);
            float d21 = fmaxf(x2s[1] + s2 - 2.f * dot1, 0.f);
            float d22 = fmaxf(x2s[2] + s2 - 2.f * dot2, 0.f);
            float d23 = fmaxf(x2s[3] + s2 - 2.f * dot3, 0.f);
            infl[(size_t)(b * Nn + n0 + 0) * Ss + s] = expf(d20 * inv) * imp;
            infl[(size_t)(b * Nn + n0 + 1) * Ss + s] = expf(d21 * inv) * imp;
            infl[(size_t)(b * Nn + n0 + 2) * Ss + s] = expf(d22 * inv) * imp;
            infl[(size_t)(b * Nn + n0 + 3) * Ss + s] = expf(d23 * inv) * imp;
        }
    }
}

__global__ __launch_bounds__(256) void total_kernel(
    const float* __restrict__ infl, float* __restrict__ total)
{
    __shared__ float red[8];
    int s = blockIdx.x, b = blockIdx.y, tid = threadIdx.x;
    float acc = 0.f;
    for (int n = tid; n < Nn; n += 256) acc += infl[(size_t)(b * Nn + n) * Ss + s];
#pragma unroll
    for (int off = 16; off; off >>= 1) acc += __shfl_xor_sync(0xffffffffu, acc, off);
    if ((tid & 31) == 0) red[tid >> 5] = acc;
    __syncthreads();
    if (tid == 0) {
        float t = 0.f;
#pragma unroll
        for (int i = 0; i < 8; i++) t += red[i];
        total[b * Ss + s] = fmaxf(t, 1e-8f);
    }
}

__global__ __launch_bounds__(256) void gather_kernel(
    const float* __restrict__ x, const float* __restrict__ infl,
    const float* __restrict__ total, float* __restrict__ gath)
{
    int s = blockIdx.x, b = blockIdx.y, tid = threadIdx.x;
    float acc[4] = {0.f, 0.f, 0.f, 0.f};
    for (int n = 0; n < Nn; n++) {
        float wv = __ldg(&infl[(size_t)(b * Nn + n) * Ss + s]);
        if (wv != 0.f) {
            const float* xr = &x[(size_t)(b * Nn + n) * Dd];
#pragma unroll
            for (int i = 0; i < 4; i++) acc[i] += wv * xr[tid + 256 * i];
        }
    }
    float inv = 1.f / total[b * Ss + s];
#pragma unroll
    for (int i = 0; i < 4; i++)
        gath[(size_t)(b * Ss + s) * Dd + tid + 256 * i] = acc[i] * inv;
}

__global__ __launch_bounds__(128) void trans_kernel(
    const float* __restrict__ enc, const float* __restrict__ Wt,
    const float* __restrict__ bt, float* __restrict__ trans)
{
    int s = blockIdx.x;
    int e = blockIdx.y * 128 + threadIdx.x;
    const float* wp = &Wt[(size_t)s * DbC * DbC];
    const float* e0 = &enc[(size_t)(0 * Ss + s) * DbC];
    const float* e1 = &enc[(size_t)(1 * Ss + s) * DbC];
    float a0 = 0.f, a1 = 0.f;
    for (int d = 0; d < DbC; d++) {
        float wv = wp[(size_t)d * DbC + e];
        a0 += e0[d] * wv;
        a1 += e1[d] * wv;
    }
    float bv = bt[s * DbC + e];
    trans[(size_t)(0 * Ss + s) * DbC + e] = a0 + bv;
    trans[(size_t)(1 * Ss + s) * DbC + e] = a1 + bv;
}

// blend: 8 tokens/block + zero-skip (R6 version — dec L2 traffic /8)
__global__ __launch_bounds__(256) void flow_blend_kernel(
    const float* __restrict__ infl, const float* __restrict__ dec,
    const float* __restrict__ gate, const float* __restrict__ stdo,
    float* __restrict__ blend)
{
    __shared__ float is[8][Ss];
    const int n0 = blockIdx.x * 8, b = blockIdx.y, tid = threadIdx.x;
    for (int i = tid; i < 8 * Ss; i += 256)
        is[i >> 6][i & 63] = infl[(size_t)(b * Nn + n0 + (i >> 6)) * Ss + (i & 63)];
    __syncthreads();

    float acc[8][4];
#pragma unroll
    for (int tk = 0; tk < 8; tk++)
#pragma unroll
        for (int i = 0; i < 4; i++) acc[tk][i] = 0.f;

    for (int s = 0; s < Ss; s++) {
        float w0 = is[0][s], w1 = is[1][s], w2 = is[2][s], w3 = is[3][s];
        float w4 = is[4][s], w5 = is[5][s], w6 = is[6][s], w7 = is[7][s];
        if ((w0 != 0.f) | (w1 != 0.f) | (w2 != 0.f) | (w3 != 0.f) |
            (w4 != 0.f) | (w5 != 0.f) | (w6 != 0.f) | (w7 != 0.f)) {
            const float* dr = &dec[(size_t)(b * Ss + s) * Dd];
#pragma unroll
            for (int i = 0; i < 4; i++) {
                float dv = dr[tid + 256 * i];
                acc[0][i] += w0 * dv; acc[1][i] += w1 * dv;
                acc[2][i] += w2 * dv; acc[3][i] += w3 * dv;
                acc[4][i] += w4 * dv; acc[5][i] += w5 * dv;
                acc[6][i] += w6 * dv; acc[7][i] += w7 * dv;
            }
        }
    }

#pragma unroll
    for (int tk = 0; tk < 8; tk++) {
#pragma unroll
        for (int i = 0; i < 4; i++) {
            size_t idx = (size_t)(b * Nn + n0 + tk) * Dd + tid + 256 * i;
            blend[idx] = 0.6f * stdo[idx] + 0.4f * acc[tk][i] * gate[idx];
        }
    }
}

// ============================================================
extern "C" void kernel_launch(void* const* d_in, const int* in_sizes, int n_in,
                              void* d_out, int out_size)
{
    const float* x    = (const float*)d_in[0];
    const float* Wq   = (const float*)d_in[1];
    const float* Wk   = (const float*)d_in[2];
    const float* Wv   = (const float*)d_in[3];
    const float* Wo   = (const float*)d_in[4];
    const float* sp   = (const float*)d_in[5];
    const float* ssc  = (const float*)d_in[6];
    const float* simp = (const float*)d_in[7];
    const float* We   = (const float*)d_in[8];
    const float* be   = (const float*)d_in[9];
    const float* Wt   = (const float*)d_in[10];
    const float* bt   = (const float*)d_in[11];
    const float* Wd   = (const float*)d_in[12];
    const float* bd   = (const float*)d_in[13];
    const float* Wg   = (const float*)d_in[14];
    const float* bg   = (const float*)d_in[15];

    float *Qp, *Kp, *Vp, *Gp, *Stdp, *Inflp, *Totp, *Gathp, *Encp, *Transp, *Decp, *Blendp;
    cudaGetSymbolAddress((void**)&Qp, g_Q);
    cudaGetSymbolAddress((void**)&Kp, g_K);
    cudaGetSymbolAddress((void**)&Vp, g_V);
    cudaGetSymbolAddress((void**)&Gp, g_G);
    cudaGetSymbolAddress((void**)&Stdp, g_std);
    cudaGetSymbolAddress((void**)&Inflp, g_infl);
    cudaGetSymbolAddress((void**)&Totp, g_total);
    cudaGetSymbolAddress((void**)&Gathp, g_gath);
    cudaGetSymbolAddress((void**)&Encp, g_enc);
    cudaGetSymbolAddress((void**)&Transp, g_trans);
    cudaGetSymbolAddress((void**)&Decp, g_dec);
    cudaGetSymbolAddress((void**)&Blendp, g_blend);

    const int M = Bb * Nn;   // 2048

    // ---- fused Q/K/V/Gate projection ----
    {
        GArgs a;
        a.A = x; a.K = Dd; a.segN = Dd;
        a.B[0] = Wq; a.B[1] = Wk; a.B[2] = Wv; a.B[3] = Wg;
        a.bias[0] = nullptr; a.bias[1] = nullptr; a.bias[2] = nullptr; a.bias[3] = bg;
        a.C[0] = Qp; a.C[1] = Kp; a.C[2] = Vp; a.C[3] = Gp;
        a.epi[0] = 0; a.epi[1] = 0; a.epi[2] = 0; a.epi[3] = 1;
        tf32_gemm<<<dim3(32, M / 128), 256>>>(a);
    }

    attn_mma_kernel<<<dim3(Nn / 128, Bb * Hh), 256>>>(Qp, Kp, Vp, Stdp);

    infl_kernel<<<dim3(Nn / 4, Bb), 256>>>(x, sp, ssc, simp, Inflp);
    total_kernel<<<dim3(Ss, Bb), 256>>>(Inflp, Totp);
    gather_kernel<<<dim3(Ss, Bb), 256>>>(x, Inflp, Totp, Gathp);

    {
        GArgs a;
        a.A = Gathp; a.K = Dd; a.segN = DbC;
        for (int i = 0; i < 4; i++) { a.B[i] = We; a.bias[i] = be; a.C[i] = Encp; a.epi[i] = 2; }
        tf32_gemm<<<dim3(DbC / 128, 1), 256>>>(a);
    }

    trans_kernel<<<dim3(Ss, DbC / 128), 128>>>(Encp, Wt, bt, Transp);

    {
        GArgs a;
        a.A = Transp; a.K = DbC; a.segN = Dd;
        for (int i = 0; i < 4; i++) { a.B[i] = Wd; a.bias[i] = bd; a.C[i] = Decp; a.epi[i] = 3; }
        tf32_gemm<<<dim3(Dd / 128, 1), 256>>>(a);
    }

    flow_blend_kernel<<<dim3(Nn / 8, Bb), 256>>>(Inflp, Decp, Gp, Stdp, Blendp);

    {
        GArgs a;
        a.A = Blendp; a.K = Dd; a.segN = Dd;
        for (int i = 0; i < 4; i++) { a.B[i] = Wo; a.bias[i] = nullptr; a.C[i] = (float*)d_out; a.epi[i] = 0; }
        tf32_gemm<<<dim3(Dd / 128, M / 128), 256>>>(a);
    }
}

// round 8
// speedup vs baseline: 1.5649x; 1.1123x over previous
#include <cuda_runtime.h>
#include <cstdint>

#define Bb 2
#define Nn 1024
#define Dd 1024
#define Hh 16
#define DhC 64
#define Ss 64
#define DbC 512

// -------- scratch (static device globals) --------
__device__ float g_Q[Bb*Nn*Dd];
__device__ float g_K[Bb*Nn*Dd];
__device__ float g_V[Bb*Nn*Dd];
__device__ float g_G[Bb*Nn*Dd];
__device__ float g_std[Bb*Nn*Dd];
__device__ float g_infl[Bb*Nn*Ss];
__device__ float g_total[Bb*Ss];
__device__ float g_gath[Bb*Ss*Dd];
__device__ float g_enc[Bb*Ss*DbC];
__device__ float g_trans[Bb*Ss*DbC];
__device__ float g_dec[Bb*Ss*Dd];
__device__ float g_blend[Bb*Nn*Dd];

__device__ __forceinline__ uint32_t f2tf32(float x) {
    uint32_t r;
    asm("cvt.rna.tf32.f32 %0, %1;" : "=r"(r) : "f"(x));
    return r;
}
__device__ __forceinline__ float tfhi(float x) {
    return __uint_as_float(__float_as_uint(x) & 0xFFFFE000u);
}
__device__ __forceinline__ void mma_tf32(float* c,
    uint32_t a0, uint32_t a1, uint32_t a2, uint32_t a3,
    uint32_t b0, uint32_t b1)
{
    asm volatile(
        "mma.sync.aligned.m16n8k8.row.col.f32.tf32.tf32.f32 "
        "{%0,%1,%2,%3},{%4,%5,%6,%7},{%8,%9},{%0,%1,%2,%3};"
        : "+f"(c[0]), "+f"(c[1]), "+f"(c[2]), "+f"(c[3])
        : "r"(a0), "r"(a1), "r"(a2), "r"(a3), "r"(b0), "r"(b1));
}
#define FU(x) __float_as_uint(x)

// ============================================================
// tf32 mma.sync GEMM with per-segment pass count (1 or 3).
// C[M, segN] = A[M,K] @ B[K,segN]; epi: 0 none, 1 sigmoid, 2 relu, 3 +bias
// ============================================================
struct GArgs {
    const float* A;
    const float* B[4];
    const float* bias[4];
    float*       C[4];
    int K;
    int segN;
    int epi[4];
    int np[4];    // passes: 1 (rounded single) or 3 (hi/lo split)
};

#define SPAD 140

__global__ __launch_bounds__(256, 2) void tf32_gemm(GArgs g)
{
    __shared__ float As[16][SPAD];
    __shared__ float Bs[16][SPAD];

    const int tid = threadIdx.x;
    const int warp = tid >> 5;
    const int lane = tid & 31;
    const int lr = lane >> 2;
    const int lc = lane & 3;
    const int wm = warp >> 2;
    const int wn = warp & 3;

    const int seg    = (blockIdx.x * 128) / g.segN;
    const int colSeg = (blockIdx.x * 128) % g.segN;
    const int rowBase = blockIdx.y * 128;
    const float* __restrict__ Bp   = g.B[seg];
    const float* __restrict__ bias = g.bias[seg];
    float* __restrict__ Cp         = g.C[seg];
    const int epi  = g.epi[seg];
    const bool p3  = (g.np[seg] == 3);
    const int K    = g.K;
    const int segN = g.segN;

    const int aRow0 = tid >> 2;
    const int aCol0 = (tid & 3) << 2;
    const int bRow0 = tid >> 5;
    const int bCol0 = (tid & 31) << 2;

    float acc[4][4][4];
#pragma unroll
    for (int i = 0; i < 4; i++)
#pragma unroll
        for (int j = 0; j < 4; j++)
#pragma unroll
            for (int q = 0; q < 4; q++) acc[i][j][q] = 0.f;

    const int T = K >> 4;
    float4 sa[2], sb[2];
#pragma unroll
    for (int i = 0; i < 2; i++) {
        sa[i] = *(const float4*)&g.A[(size_t)(rowBase + aRow0 + i * 64) * K + aCol0];
        sb[i] = *(const float4*)&Bp[(size_t)(bRow0 + i * 8) * segN + colSeg + bCol0];
    }

    for (int t = 0; t < T; t++) {
#pragma unroll
        for (int i = 0; i < 2; i++) {
            int r = aRow0 + i * 64;
            As[aCol0 + 0][r] = sa[i].x;
            As[aCol0 + 1][r] = sa[i].y;
            As[aCol0 + 2][r] = sa[i].z;
            As[aCol0 + 3][r] = sa[i].w;
            *(float4*)&Bs[bRow0 + i * 8][bCol0] = sb[i];
        }
        __syncthreads();

        if (t + 1 < T) {
            int k0 = (t + 1) * 16;
#pragma unroll
            for (int i = 0; i < 2; i++) {
                sa[i] = *(const float4*)&g.A[(size_t)(rowBase + aRow0 + i * 64) * K + k0 + aCol0];
                sb[i] = *(const float4*)&Bp[(size_t)(k0 + bRow0 + i * 8) * segN + colSeg + bCol0];
            }
        }

        if (p3) {
#pragma unroll
            for (int kk = 0; kk < 16; kk += 8) {
                uint32_t bh[4][2], bl[4][2];
#pragma unroll
                for (int nt = 0; nt < 4; nt++) {
                    int n0 = wn * 32 + nt * 8 + lr;
                    float b0 = Bs[kk + lc][n0];
                    float b1 = Bs[kk + 4 + lc][n0];
                    bh[nt][0] = f2tf32(b0);
                    bl[nt][0] = f2tf32(b0 - __uint_as_float(bh[nt][0]));
                    bh[nt][1] = f2tf32(b1);
                    bl[nt][1] = f2tf32(b1 - __uint_as_float(bh[nt][1]));
                }
#pragma unroll
                for (int mt = 0; mt < 4; mt++) {
                    int m0 = wm * 64 + mt * 16;
                    float a0 = As[kk + lc][m0 + lr];
                    float a1 = As[kk + lc][m0 + lr + 8];
                    float a2 = As[kk + 4 + lc][m0 + lr];
                    float a3 = As[kk + 4 + lc][m0 + lr + 8];
                    uint32_t ah0 = f2tf32(a0), ah1 = f2tf32(a1), ah2 = f2tf32(a2), ah3 = f2tf32(a3);
                    uint32_t al0 = f2tf32(a0 - __uint_as_float(ah0));
                    uint32_t al1 = f2tf32(a1 - __uint_as_float(ah1));
                    uint32_t al2 = f2tf32(a2 - __uint_as_float(ah2));
                    uint32_t al3 = f2tf32(a3 - __uint_as_float(ah3));
#pragma unroll
                    for (int nt = 0; nt < 4; nt++) {
                        mma_tf32(acc[mt][nt], ah0, ah1, ah2, ah3, bh[nt][0], bh[nt][1]);
                        mma_tf32(acc[mt][nt], ah0, ah1, ah2, ah3, bl[nt][0], bl[nt][1]);
                        mma_tf32(acc[mt][nt], al0, al1, al2, al3, bh[nt][0], bh[nt][1]);
                    }
                }
            }
        } else {
            // single-pass (rounded tf32)
#pragma unroll
            for (int kk = 0; kk < 16; kk += 8) {
                uint32_t bh[4][2];
#pragma unroll
                for (int nt = 0; nt < 4; nt++) {
                    int n0 = wn * 32 + nt * 8 + lr;
                    bh[nt][0] = f2tf32(Bs[kk + lc][n0]);
                    bh[nt][1] = f2tf32(Bs[kk + 4 + lc][n0]);
                }
#pragma unroll
                for (int mt = 0; mt < 4; mt++) {
                    int m0 = wm * 64 + mt * 16;
                    uint32_t ah0 = f2tf32(As[kk + lc][m0 + lr]);
                    uint32_t ah1 = f2tf32(As[kk + lc][m0 + lr + 8]);
                    uint32_t ah2 = f2tf32(As[kk + 4 + lc][m0 + lr]);
                    uint32_t ah3 = f2tf32(As[kk + 4 + lc][m0 + lr + 8]);
#pragma unroll
                    for (int nt = 0; nt < 4; nt++)
                        mma_tf32(acc[mt][nt], ah0, ah1, ah2, ah3, bh[nt][0], bh[nt][1]);
                }
            }
        }
        __syncthreads();
    }

#pragma unroll
    for (int mt = 0; mt < 4; mt++) {
#pragma unroll
        for (int nt = 0; nt < 4; nt++) {
            int col = colSeg + wn * 32 + nt * 8 + 2 * lc;
            float b0 = 0.f, b1 = 0.f;
            if (epi != 0) { b0 = bias[col]; b1 = bias[col + 1]; }
#pragma unroll
            for (int half = 0; half < 2; half++) {
                int row = rowBase + wm * 64 + mt * 16 + lr + half * 8;
                float v0 = acc[mt][nt][half * 2 + 0];
                float v1 = acc[mt][nt][half * 2 + 1];
                if (epi == 1) {
                    v0 = 1.f / (1.f + expf(-(v0 + b0)));
                    v1 = 1.f / (1.f + expf(-(v1 + b1)));
                } else if (epi == 2) {
                    v0 = fmaxf(v0 + b0, 0.f);
                    v1 = fmaxf(v1 + b1, 0.f);
                } else if (epi == 3) {
                    v0 += b0; v1 += b1;
                }
                float2 o; o.x = v0; o.y = v1;
                *(float2*)&Cp[(size_t)row * segN + col] = o;
            }
        }
    }
}

// ============================================================
// Tensor-core flash attention: S=QK^T single-pass tf32 (rounded),
// P@V 3-pass (precision-critical linear path).
// ============================================================
__global__ __launch_bounds__(256, 1) void attn_mma_kernel(
    const float* __restrict__ Q, const float* __restrict__ K,
    const float* __restrict__ V, float* __restrict__ O)
{
    __shared__ float Ks[64][68];
    __shared__ float Vs[64][72];

    const int tid = threadIdx.x;
    const int warp = tid >> 5;
    const int lane = tid & 31;
    const int g = lane >> 2;
    const int t = lane & 3;

    const int qb = blockIdx.x * 128;
    const int b = blockIdx.y >> 4, h = blockIdx.y & 15;
    const float* Qb = Q + (size_t)b * Nn * Dd + h * DhC;
    const float* Kb = K + (size_t)b * Nn * Dd + h * DhC;
    const float* Vb = V + (size_t)b * Nn * Dd + h * DhC;

    // Q fragments: pre-scaled, rounded single tf32 (no lo)
    const int r0 = qb + warp * 16 + g;
    uint32_t qh[8][4];
#pragma unroll
    for (int c = 0; c < 8; c++) {
        qh[c][0] = f2tf32(Qb[(size_t)r0 * Dd + 8 * c + t] * 0.125f);
        qh[c][1] = f2tf32(Qb[(size_t)(r0 + 8) * Dd + 8 * c + t] * 0.125f);
        qh[c][2] = f2tf32(Qb[(size_t)r0 * Dd + 8 * c + t + 4] * 0.125f);
        qh[c][3] = f2tf32(Qb[(size_t)(r0 + 8) * Dd + 8 * c + t + 4] * 0.125f);
    }

    float m0 = -1e30f, m1 = -1e30f, l0 = 0.f, l1 = 0.f;
    float o[8][4];
#pragma unroll
    for (int j = 0; j < 8; j++)
#pragma unroll
        for (int q = 0; q < 4; q++) o[j][q] = 0.f;

    float4 kreg[4], vreg[4];
#pragma unroll
    for (int i = 0; i < 4; i++) {
        int f = tid + i * 256;
        int r = f >> 4, c4 = (f & 15) << 2;
        kreg[i] = *(const float4*)&Kb[(size_t)r * Dd + c4];
        vreg[i] = *(const float4*)&Vb[(size_t)r * Dd + c4];
    }

    const int src_lo = (lane & ~3) | (t >> 1);
    const int src_hi = src_lo + 2;
    const bool odd = (t & 1);

    for (int kt = 0; kt < 16; kt++) {
        __syncthreads();
#pragma unroll
        for (int i = 0; i < 4; i++) {
            int f = tid + i * 256;
            int r = f >> 4, c4 = (f & 15) << 2;
            *(float4*)&Ks[r][c4] = kreg[i];
            *(float4*)&Vs[r][c4] = vreg[i];
        }
        __syncthreads();

        if (kt < 15) {
#pragma unroll
            for (int i = 0; i < 4; i++) {
                int f = tid + i * 256;
                int r = f >> 4, c4 = (f & 15) << 2;
                kreg[i] = *(const float4*)&Kb[(size_t)((kt + 1) * 64 + r) * Dd + c4];
                vreg[i] = *(const float4*)&Vb[(size_t)((kt + 1) * 64 + r) * Dd + c4];
            }
        }

        // ---- S = Q @ K^T : single-pass rounded tf32 ----
        float s[8][4];
#pragma unroll
        for (int j = 0; j < 8; j++)
#pragma unroll
            for (int q = 0; q < 4; q++) s[j][q] = 0.f;

#pragma unroll
        for (int c = 0; c < 8; c++) {
#pragma unroll
            for (int j = 0; j < 8; j++) {
                uint32_t ubh0 = f2tf32(Ks[8 * j + g][8 * c + t]);
                uint32_t ubh1 = f2tf32(Ks[8 * j + g][8 * c + t + 4]);
                mma_tf32(s[j], qh[c][0], qh[c][1], qh[c][2], qh[c][3], ubh0, ubh1);
            }
        }

        // ---- online softmax ----
        float mx0 = -1e30f, mx1 = -1e30f;
#pragma unroll
        for (int j = 0; j < 8; j++) {
            mx0 = fmaxf(mx0, fmaxf(s[j][0], s[j][1]));
            mx1 = fmaxf(mx1, fmaxf(s[j][2], s[j][3]));
        }
        mx0 = fmaxf(mx0, __shfl_xor_sync(0xffffffffu, mx0, 1));
        mx0 = fmaxf(mx0, __shfl_xor_sync(0xffffffffu, mx0, 2));
        mx1 = fmaxf(mx1, __shfl_xor_sync(0xffffffffu, mx1, 1));
        mx1 = fmaxf(mx1, __shfl_xor_sync(0xffffffffu, mx1, 2));
        float mn0 = fmaxf(m0, mx0), mn1 = fmaxf(m1, mx1);
        float al0 = __expf(m0 - mn0), al1 = __expf(m1 - mn1);
        m0 = mn0; m1 = mn1;
        float rs0 = 0.f, rs1 = 0.f;
#pragma unroll
        for (int j = 0; j < 8; j++) {
            s[j][0] = __expf(s[j][0] - mn0); rs0 += s[j][0];
            s[j][1] = __expf(s[j][1] - mn0); rs0 += s[j][1];
            s[j][2] = __expf(s[j][2] - mn1); rs1 += s[j][2];
            s[j][3] = __expf(s[j][3] - mn1); rs1 += s[j][3];
        }
        l0 = l0 * al0 + rs0;
        l1 = l1 * al1 + rs1;
#pragma unroll
        for (int j = 0; j < 8; j++) {
            o[j][0] *= al0; o[j][1] *= al0; o[j][2] *= al1; o[j][3] *= al1;
        }

        // ---- O += P @ V : 3-pass (linear precision path) ----
#pragma unroll
        for (int c = 0; c < 8; c++) {
            float e00 = __shfl_sync(0xffffffffu, s[c][0], src_lo);
            float e01 = __shfl_sync(0xffffffffu, s[c][1], src_lo);
            float e20 = __shfl_sync(0xffffffffu, s[c][2], src_lo);
            float e21 = __shfl_sync(0xffffffffu, s[c][3], src_lo);
            float f00 = __shfl_sync(0xffffffffu, s[c][0], src_hi);
            float f01 = __shfl_sync(0xffffffffu, s[c][1], src_hi);
            float f20 = __shfl_sync(0xffffffffu, s[c][2], src_hi);
            float f21 = __shfl_sync(0xffffffffu, s[c][3], src_hi);
            float a0 = odd ? e01 : e00;
            float a1 = odd ? e21 : e20;
            float a2 = odd ? f01 : f00;
            float a3 = odd ? f21 : f20;
            float ah0 = tfhi(a0), ah1 = tfhi(a1), ah2 = tfhi(a2), ah3 = tfhi(a3);
            uint32_t uah0 = FU(ah0), uah1 = FU(ah1), uah2 = FU(ah2), uah3 = FU(ah3);
            uint32_t ual0 = FU(a0 - ah0), ual1 = FU(a1 - ah1);
            uint32_t ual2 = FU(a2 - ah2), ual3 = FU(a3 - ah3);
#pragma unroll
            for (int j = 0; j < 8; j++) {
                float b0 = Vs[8 * c + t][8 * j + g];
                float b1 = Vs[8 * c + t + 4][8 * j + g];
                float bh0 = tfhi(b0), bh1 = tfhi(b1);
                uint32_t ubh0 = FU(bh0), ubh1 = FU(bh1);
                uint32_t ubl0 = FU(b0 - bh0), ubl1 = FU(b1 - bh1);
                mma_tf32(o[j], uah0, uah1, uah2, uah3, ubh0, ubh1);
                mma_tf32(o[j], uah0, uah1, uah2, uah3, ubl0, ubl1);
                mma_tf32(o[j], ual0, ual1, ual2, ual3, ubh0, ubh1);
            }
        }
    }

    l0 += __shfl_xor_sync(0xffffffffu, l0, 1);
    l0 += __shfl_xor_sync(0xffffffffu, l0, 2);
    l1 += __shfl_xor_sync(0xffffffffu, l1, 1);
    l1 += __shfl_xor_sync(0xffffffffu, l1, 2);
    float inv0 = 1.f / l0, inv1 = 1.f / l1;
#pragma unroll
    for (int j = 0; j < 8; j++) {
        int col = h * DhC + 8 * j + 2 * t;
        float2 w0; w0.x = o[j][0] * inv0; w0.y = o[j][1] * inv0;
        float2 w1; w1.x = o[j][2] * inv1; w1.y = o[j][3] * inv1;
        *(float2*)&O[(size_t)(b * Nn + r0) * Dd + col] = w0;
        *(float2*)&O[(size_t)(b * Nn + r0 + 8) * Dd + col] = w1;
    }
}

// ============================================================
// Splat pipeline (R7 versions)
// ============================================================
__global__ __launch_bounds__(256) void infl_kernel(
    const float* __restrict__ x, const float* __restrict__ sp,
    const float* __restrict__ sscale, const float* __restrict__ simp,
    float* __restrict__ infl)
{
    __shared__ float xs[4][Dd];
    __shared__ float xred[8][4];
    __shared__ float x2s[4];
    const int n0 = blockIdx.x * 4, b = blockIdx.y;
    const int tid = threadIdx.x;
    const int lane = tid & 31, w = tid >> 5;

    float p2[4] = {0.f, 0.f, 0.f, 0.f};
#pragma unroll
    for (int i = 0; i < 16; i++) {
        int idx = tid + i * 256;
        int tok = idx >> 10, d = idx & 1023;
        float v = x[(size_t)(b * Nn + n0 + tok) * Dd + d];
        xs[tok][d] = v;
        p2[tok] += v * v;
    }
#pragma unroll
    for (int tok = 0; tok < 4; tok++) {
        float v = p2[tok];
#pragma unroll
        for (int off = 16; off; off >>= 1) v += __shfl_xor_sync(0xffffffffu, v, off);
        if (lane == 0) xred[w][tok] = v;
    }
    __syncthreads();
    if (tid < 4) {
        float v = 0.f;
#pragma unroll
        for (int i = 0; i < 8; i++) v += xred[i][tid];
        x2s[tid] = v;
    }
    __syncthreads();

    for (int p = 0; p < 8; p++) {
        int s = w + 8 * p;
        const float* spr = &sp[(size_t)s * Dd];
        float dot0 = 0.f, dot1 = 0.f, dot2 = 0.f, dot3 = 0.f, s2 = 0.f;
        for (int d = lane; d < Dd; d += 32) {
            float pv = spr[d];
            s2 += pv * pv;
            dot0 += xs[0][d] * pv;
            dot1 += xs[1][d] * pv;
            dot2 += xs[2][d] * pv;
            dot3 += xs[3][d] * pv;
        }
#pragma unroll
        for (int off = 16; off; off >>= 1) {
            dot0 += __shfl_xor_sync(0xffffffffu, dot0, off);
            dot1 += __shfl_xor_sync(0xffffffffu, dot1, off);
            dot2 += __shfl_xor_sync(0xffffffffu, dot2, off);
            dot3 += __shfl_xor_sync(0xffffffffu, dot3, off);
            s2   += __shfl_xor_sync(0xffffffffu, s2, off);
        }
        if (lane == 0) {
            float sc = fmaxf(fabsf(sscale[s]), 1e-6f);
            float inv = -0.5f / (sc * sc);
            float imp = fabsf(simp[s]);
            float d20 = fmaxf(x2s[0] + s2 - 2.f * dot0, 0.f);
            float d21 = fmaxf(x2s[1] + s2 - 2.f * dot1, 0.f);
            float d22 = fmaxf(x2s[2] + s2 - 2.f * dot2, 0.f);
            float d23 = fmaxf(x2s[3] + s2 - 2.f * dot3, 0.f);
            infl[(size_t)(b * Nn + n0 + 0) * Ss + s] = expf(d20 * inv) * imp;
            infl[(size_t)(b * Nn + n0 + 1) * Ss + s] = expf(d21 * inv) * imp;
            infl[(size_t)(b * Nn + n0 + 2) * Ss + s] = expf(d22 * inv) * imp;
            infl[(size_t)(b * Nn + n0 + 3) * Ss + s] = expf(d23 * inv) * imp;
        }
    }
}

__global__ __launch_bounds__(256) void total_kernel(
    const float* __restrict__ infl, float* __restrict__ total)
{
    __shared__ float red[8];
    int s = blockIdx.x, b = blockIdx.y, tid = threadIdx.x;
    float acc = 0.f;
    for (int n = tid; n < Nn; n += 256) acc += infl[(size_t)(b * Nn + n) * Ss + s];
#pragma unroll
    for (int off = 16; off; off >>= 1) acc += __shfl_xor_sync(0xffffffffu, acc, off);
    if ((tid & 31) == 0) red[tid >> 5] = acc;
    __syncthreads();
    if (tid == 0) {
        float t = 0.f;
#pragma unroll
        for (int i = 0; i < 8; i++) t += red[i];
        total[b * Ss + s] = fmaxf(t, 1e-8f);
    }
}

__global__ __launch_bounds__(256) void gather_kernel(
    const float* __restrict__ x, const float* __restrict__ infl,
    const float* __restrict__ total, float* __restrict__ gath)
{
    int s = blockIdx.x, b = blockIdx.y, tid = threadIdx.x;
    float acc[4] = {0.f, 0.f, 0.f, 0.f};
    for (int n = 0; n < Nn; n++) {
        float wv = __ldg(&infl[(size_t)(b * Nn + n) * Ss + s]);
        if (wv != 0.f) {
            const float* xr = &x[(size_t)(b * Nn + n) * Dd];
#pragma unroll
            for (int i = 0; i < 4; i++) acc[i] += wv * xr[tid + 256 * i];
        }
    }
    float inv = 1.f / total[b * Ss + s];
#pragma unroll
    for (int i = 0; i < 4; i++)
        gath[(size_t)(b * Ss + s) * Dd + tid + 256 * i] = acc[i] * inv;
}

__global__ __launch_bounds__(128) void trans_kernel(
    const float* __restrict__ enc, const float* __restrict__ Wt,
    const float* __restrict__ bt, float* __restrict__ trans)
{
    int s = blockIdx.x;
    int e = blockIdx.y * 128 + threadIdx.x;
    const float* wp = &Wt[(size_t)s * DbC * DbC];
    const float* e0 = &enc[(size_t)(0 * Ss + s) * DbC];
    const float* e1 = &enc[(size_t)(1 * Ss + s) * DbC];
    float a0 = 0.f, a1 = 0.f;
    for (int d = 0; d < DbC; d++) {
        float wv = wp[(size_t)d * DbC + e];
        a0 += e0[d] * wv;
        a1 += e1[d] * wv;
    }
    float bv = bt[s * DbC + e];
    trans[(size_t)(0 * Ss + s) * DbC + e] = a0 + bv;
    trans[(size_t)(1 * Ss + s) * DbC + e] = a1 + bv;
}

__global__ __launch_bounds__(256) void flow_blend_kernel(
    const float* __restrict__ infl, const float* __restrict__ dec,
    const float* __restrict__ gate, const float* __restrict__ stdo,
    float* __restrict__ blend)
{
    __shared__ float is[8][Ss];
    const int n0 = blockIdx.x * 8, b = blockIdx.y, tid = threadIdx.x;
    for (int i = tid; i < 8 * Ss; i += 256)
        is[i >> 6][i & 63] = infl[(size_t)(b * Nn + n0 + (i >> 6)) * Ss + (i & 63)];
    __syncthreads();

    float acc[8][4];
#pragma unroll
    for (int tk = 0; tk < 8; tk++)
#pragma unroll
        for (int i = 0; i < 4; i++) acc[tk][i] = 0.f;

    for (int s = 0; s < Ss; s++) {
        float w0 = is[0][s], w1 = is[1][s], w2 = is[2][s], w3 = is[3][s];
        float w4 = is[4][s], w5 = is[5][s], w6 = is[6][s], w7 = is[7][s];
        if ((w0 != 0.f) | (w1 != 0.f) | (w2 != 0.f) | (w3 != 0.f) |
            (w4 != 0.f) | (w5 != 0.f) | (w6 != 0.f) | (w7 != 0.f)) {
            const float* dr = &dec[(size_t)(b * Ss + s) * Dd];
#pragma unroll
            for (int i = 0; i < 4; i++) {
                float dv = dr[tid + 256 * i];
                acc[0][i] += w0 * dv; acc[1][i] += w1 * dv;
                acc[2][i] += w2 * dv; acc[3][i] += w3 * dv;
                acc[4][i] += w4 * dv; acc[5][i] += w5 * dv;
                acc[6][i] += w6 * dv; acc[7][i] += w7 * dv;
            }
        }
    }

#pragma unroll
    for (int tk = 0; tk < 8; tk++) {
#pragma unroll
        for (int i = 0; i < 4; i++) {
            size_t idx = (size_t)(b * Nn + n0 + tk) * Dd + tid + 256 * i;
            blend[idx] = 0.6f * stdo[idx] + 0.4f * acc[tk][i] * gate[idx];
        }
    }
}

// ============================================================
extern "C" void kernel_launch(void* const* d_in, const int* in_sizes, int n_in,
                              void* d_out, int out_size)
{
    const float* x    = (const float*)d_in[0];
    const float* Wq   = (const float*)d_in[1];
    const float* Wk   = (const float*)d_in[2];
    const float* Wv   = (const float*)d_in[3];
    const float* Wo   = (const float*)d_in[4];
    const float* sp   = (const float*)d_in[5];
    const float* ssc  = (const float*)d_in[6];
    const float* simp = (const float*)d_in[7];
    const float* We   = (const float*)d_in[8];
    const float* be   = (const float*)d_in[9];
    const float* Wt   = (const float*)d_in[10];
    const float* bt   = (const float*)d_in[11];
    const float* Wd   = (const float*)d_in[12];
    const float* bd   = (const float*)d_in[13];
    const float* Wg   = (const float*)d_in[14];
    const float* bg   = (const float*)d_in[15];

    float *Qp, *Kp, *Vp, *Gp, *Stdp, *Inflp, *Totp, *Gathp, *Encp, *Transp, *Decp, *Blendp;
    cudaGetSymbolAddress((void**)&Qp, g_Q);
    cudaGetSymbolAddress((void**)&Kp, g_K);
    cudaGetSymbolAddress((void**)&Vp, g_V);
    cudaGetSymbolAddress((void**)&Gp, g_G);
    cudaGetSymbolAddress((void**)&Stdp, g_std);
    cudaGetSymbolAddress((void**)&Inflp, g_infl);
    cudaGetSymbolAddress((void**)&Totp, g_total);
    cudaGetSymbolAddress((void**)&Gathp, g_gath);
    cudaGetSymbolAddress((void**)&Encp, g_enc);
    cudaGetSymbolAddress((void**)&Transp, g_trans);
    cudaGetSymbolAddress((void**)&Decp, g_dec);
    cudaGetSymbolAddress((void**)&Blendp, g_blend);

    const int M = Bb * Nn;   // 2048

    // ---- fused Q/K/V/Gate projection: Q,K,G single-pass; V 3-pass ----
    {
        GArgs a;
        a.A = x; a.K = Dd; a.segN = Dd;
        a.B[0] = Wq; a.B[1] = Wk; a.B[2] = Wv; a.B[3] = Wg;
        a.bias[0] = nullptr; a.bias[1] = nullptr; a.bias[2] = nullptr; a.bias[3] = bg;
        a.C[0] = Qp; a.C[1] = Kp; a.C[2] = Vp; a.C[3] = Gp;
        a.epi[0] = 0; a.epi[1] = 0; a.epi[2] = 0; a.epi[3] = 1;
        a.np[0] = 1; a.np[1] = 1; a.np[2] = 3; a.np[3] = 1;
        tf32_gemm<<<dim3(32, M / 128), 256>>>(a);
    }

    attn_mma_kernel<<<dim3(Nn / 128, Bb * Hh), 256>>>(Qp, Kp, Vp, Stdp);

    infl_kernel<<<dim3(Nn / 4, Bb), 256>>>(x, sp, ssc, simp, Inflp);
    total_kernel<<<dim3(Ss, Bb), 256>>>(Inflp, Totp);
    gather_kernel<<<dim3(Ss, Bb), 256>>>(x, Inflp, Totp, Gathp);

    // enc (flow branch — numerically gated by infl): single-pass
    {
        GArgs a;
        a.A = Gathp; a.K = Dd; a.segN = DbC;
        for (int i = 0; i < 4; i++) { a.B[i] = We; a.bias[i] = be; a.C[i] = Encp; a.epi[i] = 2; a.np[i] = 1; }
        tf32_gemm<<<dim3(DbC / 128, 1), 256>>>(a);
    }

    trans_kernel<<<dim3(Ss, DbC / 128), 128>>>(Encp, Wt, bt, Transp);

    // dec (flow branch): single-pass
    {
        GArgs a;
        a.A = Transp; a.K = DbC; a.segN = Dd;
        for (int i = 0; i < 4; i++) { a.B[i] = Wd; a.bias[i] = bd; a.C[i] = Decp; a.epi[i] = 3; a.np[i] = 1; }
        tf32_gemm<<<dim3(Dd / 128, 1), 256>>>(a);
    }

    flow_blend_kernel<<<dim3(Nn / 8, Bb), 256>>>(Inflp, Decp, Gp, Stdp, Blendp);

    // final projection: 3-pass (output precision anchor)
    {
        GArgs a;
        a.A = Blendp; a.K = Dd; a.segN = Dd;
        for (int i = 0; i < 4; i++) { a.B[i] = Wo; a.bias[i] = nullptr; a.C[i] = (float*)d_out; a.epi[i] = 0; a.np[i] = 3; }
        tf32_gemm<<<dim3(Dd / 128, M / 128), 256>>>(a);
    }
}

// round 9
// speedup vs baseline: 1.5655x; 1.0004x over previous
#include <cuda_runtime.h>
#include <cstdint>

#define Bb 2
#define Nn 1024
#define Dd 1024
#define Hh 16
#define DhC 64
#define Ss 64
#define DbC 512

// -------- scratch (static device globals) --------
__device__ float g_Q[Bb*Nn*Dd];
__device__ float g_K[Bb*Nn*Dd];
__device__ float g_V[Bb*Nn*Dd];
__device__ float g_G[Bb*Nn*Dd];
__device__ float g_std[Bb*Nn*Dd];
__device__ float g_infl[Bb*Nn*Ss];
__device__ float g_total[Bb*Ss];
__device__ float g_gath[Bb*Ss*Dd];
__device__ float g_enc[Bb*Ss*DbC];
__device__ float g_trans[Bb*Ss*DbC];
__device__ float g_dec[Bb*Ss*Dd];
__device__ float g_blend[Bb*Nn*Dd];

__device__ __forceinline__ uint32_t f2tf32(float x) {
    uint32_t r;
    asm("cvt.rna.tf32.f32 %0, %1;" : "=r"(r) : "f"(x));
    return r;
}
__device__ __forceinline__ float tfhi(float x) {
    return __uint_as_float(__float_as_uint(x) & 0xFFFFE000u);
}
__device__ __forceinline__ void mma_tf32(float* c,
    uint32_t a0, uint32_t a1, uint32_t a2, uint32_t a3,
    uint32_t b0, uint32_t b1)
{
    asm volatile(
        "mma.sync.aligned.m16n8k8.row.col.f32.tf32.tf32.f32 "
        "{%0,%1,%2,%3},{%4,%5,%6,%7},{%8,%9},{%0,%1,%2,%3};"
        : "+f"(c[0]), "+f"(c[1]), "+f"(c[2]), "+f"(c[3])
        : "r"(a0), "r"(a1), "r"(a2), "r"(a3), "r"(b0), "r"(b1));
}
#define FU(x) __float_as_uint(x)

// ============================================================
// tf32 mma.sync GEMM with per-segment pass count (1, 2, or 3).
//  1: round(A) x round(B)           — err ~2e-4 both operands
//  2: [hi(A)+lo(A)] x round(B)      — err = B rounding only
//  3: hi/lo A x hi/lo B (drop lolo) — err ~2^-22
// C[M, segN] = A[M,K] @ B[K,segN]; epi: 0 none, 1 sigmoid, 2 relu, 3 +bias
// ============================================================
struct GArgs {
    const float* A;
    const float* B[4];
    const float* bias[4];
    float*       C[4];
    int K;
    int segN;
    int epi[4];
    int np[4];
};

#define SPAD 140

__global__ __launch_bounds__(256, 2) void tf32_gemm(GArgs g)
{
    __shared__ float As[16][SPAD];
    __shared__ float Bs[16][SPAD];

    const int tid = threadIdx.x;
    const int warp = tid >> 5;
    const int lane = tid & 31;
    const int lr = lane >> 2;
    const int lc = lane & 3;
    const int wm = warp >> 2;
    const int wn = warp & 3;

    const int seg    = (blockIdx.x * 128) / g.segN;
    const int colSeg = (blockIdx.x * 128) % g.segN;
    const int rowBase = blockIdx.y * 128;
    const float* __restrict__ Bp   = g.B[seg];
    const float* __restrict__ bias = g.bias[seg];
    float* __restrict__ Cp         = g.C[seg];
    const int epi  = g.epi[seg];
    const int np   = g.np[seg];
    const int K    = g.K;
    const int segN = g.segN;

    const int aRow0 = tid >> 2;
    const int aCol0 = (tid & 3) << 2;
    const int bRow0 = tid >> 5;
    const int bCol0 = (tid & 31) << 2;

    float acc[4][4][4];
#pragma unroll
    for (int i = 0; i < 4; i++)
#pragma unroll
        for (int j = 0; j < 4; j++)
#pragma unroll
            for (int q = 0; q < 4; q++) acc[i][j][q] = 0.f;

    const int T = K >> 4;
    float4 sa[2], sb[2];
#pragma unroll
    for (int i = 0; i < 2; i++) {
        sa[i] = *(const float4*)&g.A[(size_t)(rowBase + aRow0 + i * 64) * K + aCol0];
        sb[i] = *(const float4*)&Bp[(size_t)(bRow0 + i * 8) * segN + colSeg + bCol0];
    }

    for (int t = 0; t < T; t++) {
#pragma unroll
        for (int i = 0; i < 2; i++) {
            int r = aRow0 + i * 64;
            As[aCol0 + 0][r] = sa[i].x;
            As[aCol0 + 1][r] = sa[i].y;
            As[aCol0 + 2][r] = sa[i].z;
            As[aCol0 + 3][r] = sa[i].w;
            *(float4*)&Bs[bRow0 + i * 8][bCol0] = sb[i];
        }
        __syncthreads();

        if (t + 1 < T) {
            int k0 = (t + 1) * 16;
#pragma unroll
            for (int i = 0; i < 2; i++) {
                sa[i] = *(const float4*)&g.A[(size_t)(rowBase + aRow0 + i * 64) * K + k0 + aCol0];
                sb[i] = *(const float4*)&Bp[(size_t)(k0 + bRow0 + i * 8) * segN + colSeg + bCol0];
            }
        }

        if (np == 3) {
#pragma unroll
            for (int kk = 0; kk < 16; kk += 8) {
                uint32_t bh[4][2], bl[4][2];
#pragma unroll
                for (int nt = 0; nt < 4; nt++) {
                    int n0 = wn * 32 + nt * 8 + lr;
                    float b0 = Bs[kk + lc][n0];
                    float b1 = Bs[kk + 4 + lc][n0];
                    bh[nt][0] = f2tf32(b0);
                    bl[nt][0] = f2tf32(b0 - __uint_as_float(bh[nt][0]));
                    bh[nt][1] = f2tf32(b1);
                    bl[nt][1] = f2tf32(b1 - __uint_as_float(bh[nt][1]));
                }
#pragma unroll
                for (int mt = 0; mt < 4; mt++) {
                    int m0 = wm * 64 + mt * 16;
                    float a0 = As[kk + lc][m0 + lr];
                    float a1 = As[kk + lc][m0 + lr + 8];
                    float a2 = As[kk + 4 + lc][m0 + lr];
                    float a3 = As[kk + 4 + lc][m0 + lr + 8];
                    uint32_t ah0 = f2tf32(a0), ah1 = f2tf32(a1), ah2 = f2tf32(a2), ah3 = f2tf32(a3);
                    uint32_t al0 = f2tf32(a0 - __uint_as_float(ah0));
                    uint32_t al1 = f2tf32(a1 - __uint_as_float(ah1));
                    uint32_t al2 = f2tf32(a2 - __uint_as_float(ah2));
                    uint32_t al3 = f2tf32(a3 - __uint_as_float(ah3));
#pragma unroll
                    for (int nt = 0; nt < 4; nt++) {
                        mma_tf32(acc[mt][nt], ah0, ah1, ah2, ah3, bh[nt][0], bh[nt][1]);
                        mma_tf32(acc[mt][nt], ah0, ah1, ah2, ah3, bl[nt][0], bl[nt][1]);
                        mma_tf32(acc[mt][nt], al0, al1, al2, al3, bh[nt][0], bh[nt][1]);
                    }
                }
            }
        } else if (np == 2) {
            // split A exactly, round B: error = B rounding only
#pragma unroll
            for (int kk = 0; kk < 16; kk += 8) {
                uint32_t bh[4][2];
#pragma unroll
                for (int nt = 0; nt < 4; nt++) {
                    int n0 = wn * 32 + nt * 8 + lr;
                    bh[nt][0] = f2tf32(Bs[kk + lc][n0]);
                    bh[nt][1] = f2tf32(Bs[kk + 4 + lc][n0]);
                }
#pragma unroll
                for (int mt = 0; mt < 4; mt++) {
                    int m0 = wm * 64 + mt * 16;
                    float a0 = As[kk + lc][m0 + lr];
                    float a1 = As[kk + lc][m0 + lr + 8];
                    float a2 = As[kk + 4 + lc][m0 + lr];
                    float a3 = As[kk + 4 + lc][m0 + lr + 8];
                    uint32_t ah0 = f2tf32(a0), ah1 = f2tf32(a1), ah2 = f2tf32(a2), ah3 = f2tf32(a3);
                    uint32_t al0 = f2tf32(a0 - __uint_as_float(ah0));
                    uint32_t al1 = f2tf32(a1 - __uint_as_float(ah1));
                    uint32_t al2 = f2tf32(a2 - __uint_as_float(ah2));
                    uint32_t al3 = f2tf32(a3 - __uint_as_float(ah3));
#pragma unroll
                    for (int nt = 0; nt < 4; nt++) {
                        mma_tf32(acc[mt][nt], ah0, ah1, ah2, ah3, bh[nt][0], bh[nt][1]);
                        mma_tf32(acc[mt][nt], al0, al1, al2, al3, bh[nt][0], bh[nt][1]);
                    }
                }
            }
        } else {
#pragma unroll
            for (int kk = 0; kk < 16; kk += 8) {
                uint32_t bh[4][2];
#pragma unroll
                for (int nt = 0; nt < 4; nt++) {
                    int n0 = wn * 32 + nt * 8 + lr;
                    bh[nt][0] = f2tf32(Bs[kk + lc][n0]);
                    bh[nt][1] = f2tf32(Bs[kk + 4 + lc][n0]);
                }
#pragma unroll
                for (int mt = 0; mt < 4; mt++) {
                    int m0 = wm * 64 + mt * 16;
                    uint32_t ah0 = f2tf32(As[kk + lc][m0 + lr]);
                    uint32_t ah1 = f2tf32(As[kk + lc][m0 + lr + 8]);
                    uint32_t ah2 = f2tf32(As[kk + 4 + lc][m0 + lr]);
                    uint32_t ah3 = f2tf32(As[kk + 4 + lc][m0 + lr + 8]);
#pragma unroll
                    for (int nt = 0; nt < 4; nt++)
                        mma_tf32(acc[mt][nt], ah0, ah1, ah2, ah3, bh[nt][0], bh[nt][1]);
                }
            }
        }
        __syncthreads();
    }

#pragma unroll
    for (int mt = 0; mt < 4; mt++) {
#pragma unroll
        for (int nt = 0; nt < 4; nt++) {
            int col = colSeg + wn * 32 + nt * 8 + 2 * lc;
            float b0 = 0.f, b1 = 0.f;
            if (epi != 0) { b0 = bias[col]; b1 = bias[col + 1]; }
#pragma unroll
            for (int half = 0; half < 2; half++) {
                int row = rowBase + wm * 64 + mt * 16 + lr + half * 8;
                float v0 = acc[mt][nt][half * 2 + 0];
                float v1 = acc[mt][nt][half * 2 + 1];
                if (epi == 1) {
                    v0 = 1.f / (1.f + expf(-(v0 + b0)));
                    v1 = 1.f / (1.f + expf(-(v1 + b1)));
                } else if (epi == 2) {
                    v0 = fmaxf(v0 + b0, 0.f);
                    v1 = fmaxf(v1 + b1, 0.f);
                } else if (epi == 3) {
                    v0 += b0; v1 += b1;
                }
                float2 o; o.x = v0; o.y = v1;
                *(float2*)&Cp[(size_t)row * segN + col] = o;
            }
        }
    }
}

// ============================================================
// Tensor-core flash attention: S single-pass; P@V 2-pass
// (P exactly split hi/lo, V rounded — error = V rounding only).
// ============================================================
__global__ __launch_bounds__(256, 1) void attn_mma_kernel(
    const float* __restrict__ Q, const float* __restrict__ K,
    const float* __restrict__ V, float* __restrict__ O)
{
    __shared__ float Ks[64][68];
    __shared__ float Vs[64][72];

    const int tid = threadIdx.x;
    const int warp = tid >> 5;
    const int lane = tid & 31;
    const int g = lane >> 2;
    const int t = lane & 3;

    const int qb = blockIdx.x * 128;
    const int b = blockIdx.y >> 4, h = blockIdx.y & 15;
    const float* Qb = Q + (size_t)b * Nn * Dd + h * DhC;
    const float* Kb = K + (size_t)b * Nn * Dd + h * DhC;
    const float* Vb = V + (size_t)b * Nn * Dd + h * DhC;

    const int r0 = qb + warp * 16 + g;
    uint32_t qh[8][4];
#pragma unroll
    for (int c = 0; c < 8; c++) {
        qh[c][0] = f2tf32(Qb[(size_t)r0 * Dd + 8 * c + t] * 0.125f);
        qh[c][1] = f2tf32(Qb[(size_t)(r0 + 8) * Dd + 8 * c + t] * 0.125f);
        qh[c][2] = f2tf32(Qb[(size_t)r0 * Dd + 8 * c + t + 4] * 0.125f);
        qh[c][3] = f2tf32(Qb[(size_t)(r0 + 8) * Dd + 8 * c + t + 4] * 0.125f);
    }

    float m0 = -1e30f, m1 = -1e30f, l0 = 0.f, l1 = 0.f;
    float o[8][4];
#pragma unroll
    for (int j = 0; j < 8; j++)
#pragma unroll
        for (int q = 0; q < 4; q++) o[j][q] = 0.f;

    float4 kreg[4], vreg[4];
#pragma unroll
    for (int i = 0; i < 4; i++) {
        int f = tid + i * 256;
        int r = f >> 4, c4 = (f & 15) << 2;
        kreg[i] = *(const float4*)&Kb[(size_t)r * Dd + c4];
        vreg[i] = *(const float4*)&Vb[(size_t)r * Dd + c4];
    }

    const int src_lo = (lane & ~3) | (t >> 1);
    const int src_hi = src_lo + 2;
    const bool odd = (t & 1);

    for (int kt = 0; kt < 16; kt++) {
        __syncthreads();
#pragma unroll
        for (int i = 0; i < 4; i++) {
            int f = tid + i * 256;
            int r = f >> 4, c4 = (f & 15) << 2;
            *(float4*)&Ks[r][c4] = kreg[i];
            *(float4*)&Vs[r][c4] = vreg[i];
        }
        __syncthreads();

        if (kt < 15) {
#pragma unroll
            for (int i = 0; i < 4; i++) {
                int f = tid + i * 256;
                int r = f >> 4, c4 = (f & 15) << 2;
                kreg[i] = *(const float4*)&Kb[(size_t)((kt + 1) * 64 + r) * Dd + c4];
                vreg[i] = *(const float4*)&Vb[(size_t)((kt + 1) * 64 + r) * Dd + c4];
            }
        }

        // ---- S = Q @ K^T : single-pass rounded tf32 ----
        float s[8][4];
#pragma unroll
        for (int j = 0; j < 8; j++)
#pragma unroll
            for (int q = 0; q < 4; q++) s[j][q] = 0.f;

#pragma unroll
        for (int c = 0; c < 8; c++) {
#pragma unroll
            for (int j = 0; j < 8; j++) {
                uint32_t ubh0 = f2tf32(Ks[8 * j + g][8 * c + t]);
                uint32_t ubh1 = f2tf32(Ks[8 * j + g][8 * c + t + 4]);
                mma_tf32(s[j], qh[c][0], qh[c][1], qh[c][2], qh[c][3], ubh0, ubh1);
            }
        }

        // ---- online softmax ----
        float mx0 = -1e30f, mx1 = -1e30f;
#pragma unroll
        for (int j = 0; j < 8; j++) {
            mx0 = fmaxf(mx0, fmaxf(s[j][0], s[j][1]));
            mx1 = fmaxf(mx1, fmaxf(s[j][2], s[j][3]));
        }
        mx0 = fmaxf(mx0, __shfl_xor_sync(0xffffffffu, mx0, 1));
        mx0 = fmaxf(mx0, __shfl_xor_sync(0xffffffffu, mx0, 2));
        mx1 = fmaxf(mx1, __shfl_xor_sync(0xffffffffu, mx1, 1));
        mx1 = fmaxf(mx1, __shfl_xor_sync(0xffffffffu, mx1, 2));
        float mn0 = fmaxf(m0, mx0), mn1 = fmaxf(m1, mx1);
        float al0 = __expf(m0 - mn0), al1 = __expf(m1 - mn1);
        m0 = mn0; m1 = mn1;
        float rs0 = 0.f, rs1 = 0.f;
#pragma unroll
        for (int j = 0; j < 8; j++) {
            s[j][0] = __expf(s[j][0] - mn0); rs0 += s[j][0];
            s[j][1] = __expf(s[j][1] - mn0); rs0 += s[j][1];
            s[j][2] = __expf(s[j][2] - mn1); rs1 += s[j][2];
            s[j][3] = __expf(s[j][3] - mn1); rs1 += s[j][3];
        }
        l0 = l0 * al0 + rs0;
        l1 = l1 * al1 + rs1;
#pragma unroll
        for (int j = 0; j < 8; j++) {
            o[j][0] *= al0; o[j][1] *= al0; o[j][2] *= al1; o[j][3] *= al1;
        }

        // ---- O += P @ V : 2-pass (P split exact, V rounded) ----
#pragma unroll
        for (int c = 0; c < 8; c++) {
            float e00 = __shfl_sync(0xffffffffu, s[c][0], src_lo);
            float e01 = __shfl_sync(0xffffffffu, s[c][1], src_lo);
            float e20 = __shfl_sync(0xffffffffu, s[c][2], src_lo);
            float e21 = __shfl_sync(0xffffffffu, s[c][3], src_lo);
            float f00 = __shfl_sync(0xffffffffu, s[c][0], src_hi);
            float f01 = __shfl_sync(0xffffffffu, s[c][1], src_hi);
            float f20 = __shfl_sync(0xffffffffu, s[c][2], src_hi);
            float f21 = __shfl_sync(0xffffffffu, s[c][3], src_hi);
            float a0 = odd ? e01 : e00;
            float a1 = odd ? e21 : e20;
            float a2 = odd ? f01 : f00;
            float a3 = odd ? f21 : f20;
            uint32_t uah0 = f2tf32(a0), uah1 = f2tf32(a1), uah2 = f2tf32(a2), uah3 = f2tf32(a3);
            uint32_t ual0 = f2tf32(a0 - __uint_as_float(uah0));
            uint32_t ual1 = f2tf32(a1 - __uint_as_float(uah1));
            uint32_t ual2 = f2tf32(a2 - __uint_as_float(uah2));
            uint32_t ual3 = f2tf32(a3 - __uint_as_float(uah3));
#pragma unroll
            for (int j = 0; j < 8; j++) {
                uint32_t ubh0 = f2tf32(Vs[8 * c + t][8 * j + g]);
                uint32_t ubh1 = f2tf32(Vs[8 * c + t + 4][8 * j + g]);
                mma_tf32(o[j], uah0, uah1, uah2, uah3, ubh0, ubh1);
                mma_tf32(o[j], ual0, ual1, ual2, ual3, ubh0, ubh1);
            }
        }
    }

    l0 += __shfl_xor_sync(0xffffffffu, l0, 1);
    l0 += __shfl_xor_sync(0xffffffffu, l0, 2);
    l1 += __shfl_xor_sync(0xffffffffu, l1, 1);
    l1 += __shfl_xor_sync(0xffffffffu, l1, 2);
    float inv0 = 1.f / l0, inv1 = 1.f / l1;
#pragma unroll
    for (int j = 0; j < 8; j++) {
        int col = h * DhC + 8 * j + 2 * t;
        float2 w0; w0.x = o[j][0] * inv0; w0.y = o[j][1] * inv0;
        float2 w1; w1.x = o[j][2] * inv1; w1.y = o[j][3] * inv1;
        *(float2*)&O[(size_t)(b * Nn + r0) * Dd + col] = w0;
        *(float2*)&O[(size_t)(b * Nn + r0 + 8) * Dd + col] = w1;
    }
}

// ============================================================
// Splat pipeline (unchanged from R7/R8)
// ============================================================
__global__ __launch_bounds__(256) void infl_kernel(
    const float* __restrict__ x, const float* __restrict__ sp,
    const float* __restrict__ sscale, const float* __restrict__ simp,
    float* __restrict__ infl)
{
    __shared__ float xs[4][Dd];
    __shared__ float xred[8][4];
    __shared__ float x2s[4];
    const int n0 = blockIdx.x * 4, b = blockIdx.y;
    const int tid = threadIdx.x;
    const int lane = tid & 31, w = tid >> 5;

    float p2[4] = {0.f, 0.f, 0.f, 0.f};
#pragma unroll
    for (int i = 0; i < 16; i++) {
        int idx = tid + i * 256;
        int tok = idx >> 10, d = idx & 1023;
        float v = x[(size_t)(b * Nn + n0 + tok) * Dd + d];
        xs[tok][d] = v;
        p2[tok] += v * v;
    }
#pragma unroll
    for (int tok = 0; tok < 4; tok++) {
        float v = p2[tok];
#pragma unroll
        for (int off = 16; off; off >>= 1) v += __shfl_xor_sync(0xffffffffu, v, off);
        if (lane == 0) xred[w][tok] = v;
    }
    __syncthreads();
    if (tid < 4) {
        float v = 0.f;
#pragma unroll
        for (int i = 0; i < 8; i++) v += xred[i][tid];
        x2s[tid] = v;
    }
    __syncthreads();

    for (int p = 0; p < 8; p++) {
        int s = w + 8 * p;
        const float* spr = &sp[(size_t)s * Dd];
        float dot0 = 0.f, dot1 = 0.f, dot2 = 0.f, dot3 = 0.f, s2 = 0.f;
        for (int d = lane; d < Dd; d += 32) {
            float pv = spr[d];
            s2 += pv * pv;
            dot0 += xs[0][d] * pv;
            dot1 += xs[1][d] * pv;
            dot2 += xs[2][d] * pv;
            dot3 += xs[3][d] * pv;
        }
#pragma unroll
        for (int off = 16; off; off >>= 1) {
            dot0 += __shfl_xor_sync(0xffffffffu, dot0, off);
            dot1 += __shfl_xor_sync(0xffffffffu, dot1, off);
            dot2 += __shfl_xor_sync(0xffffffffu, dot2, off);
            dot3 += __shfl_xor_sync(0xffffffffu, dot3, off);
            s2   += __shfl_xor_sync(0xffffffffu, s2, off);
        }
        if (lane == 0) {
            float sc = fmaxf(fabsf(sscale[s]), 1e-6f);
            float inv = -0.5f / (sc * sc);
            float imp = fabsf(simp[s]);
            float d20 = fmaxf(x2s[0] + s2 - 2.f * dot0, 0.f);
            float d21 = fmaxf(x2s[1] + s2 - 2.f * dot1, 0.f);
            float d22 = fmaxf(x2s[2] + s2 - 2.f * dot2, 0.f);
            float d23 = fmaxf(x2s[3] + s2 - 2.f * dot3, 0.f);
            infl[(size_t)(b * Nn + n0 + 0) * Ss + s] = expf(d20 * inv) * imp;
            infl[(size_t)(b * Nn + n0 + 1) * Ss + s] = expf(d21 * inv) * imp;
            infl[(size_t)(b * Nn + n0 + 2) * Ss + s] = expf(d22 * inv) * imp;
            infl[(size_t)(b * Nn + n0 + 3) * Ss + s] = expf(d23 * inv) * imp;
        }
    }
}

__global__ __launch_bounds__(256) void total_kernel(
    const float* __restrict__ infl, float* __restrict__ total)
{
    __shared__ float red[8];
    int s = blockIdx.x, b = blockIdx.y, tid = threadIdx.x;
    float acc = 0.f;
    for (int n = tid; n < Nn; n += 256) acc += infl[(size_t)(b * Nn + n) * Ss + s];
#pragma unroll
    for (int off = 16; off; off >>= 1) acc += __shfl_xor_sync(0xffffffffu, acc, off);
    if ((tid & 31) == 0) red[tid >> 5] = acc;
    __syncthreads();
    if (tid == 0) {
        float t = 0.f;
#pragma unroll
        for (int i = 0; i < 8; i++) t += red[i];
        total[b * Ss + s] = fmaxf(t, 1e-8f);
    }
}

__global__ __launch_bounds__(256) void gather_kernel(
    const float* __restrict__ x, const float* __restrict__ infl,
    const float* __restrict__ total, float* __restrict__ gath)
{
    int s = blockIdx.x, b = blockIdx.y, tid = threadIdx.x;
    float acc[4] = {0.f, 0.f, 0.f, 0.f};
    for (int n = 0; n < Nn; n++) {
        float wv = __ldg(&infl[(size_t)(b * Nn + n) * Ss + s]);
        if (wv != 0.f) {
            const float* xr = &x[(size_t)(b * Nn + n) * Dd];
#pragma unroll
            for (int i = 0; i < 4; i++) acc[i] += wv * xr[tid + 256 * i];
        }
    }
    float inv = 1.f / total[b * Ss + s];
#pragma unroll
    for (int i = 0; i < 4; i++)
        gath[(size_t)(b * Ss + s) * Dd + tid + 256 * i] = acc[i] * inv;
}

__global__ __launch_bounds__(128) void trans_kernel(
    const float* __restrict__ enc, const float* __restrict__ Wt,
    const float* __restrict__ bt, float* __restrict__ trans)
{
    int s = blockIdx.x;
    int e = blockIdx.y * 128 + threadIdx.x;
    const float* wp = &Wt[(size_t)s * DbC * DbC];
    const float* e0 = &enc[(size_t)(0 * Ss + s) * DbC];
    const float* e1 = &enc[(size_t)(1 * Ss + s) * DbC];
    float a0 = 0.f, a1 = 0.f;
    for (int d = 0; d < DbC; d++) {
        float wv = wp[(size_t)d * DbC + e];
        a0 += e0[d] * wv;
        a1 += e1[d] * wv;
    }
    float bv = bt[s * DbC + e];
    trans[(size_t)(0 * Ss + s) * DbC + e] = a0 + bv;
    trans[(size_t)(1 * Ss + s) * DbC + e] = a1 + bv;
}

__global__ __launch_bounds__(256) void flow_blend_kernel(
    const float* __restrict__ infl, const float* __restrict__ dec,
    const float* __restrict__ gate, const float* __restrict__ stdo,
    float* __restrict__ blend)
{
    __shared__ float is[8][Ss];
    const int n0 = blockIdx.x * 8, b = blockIdx.y, tid = threadIdx.x;
    for (int i = tid; i < 8 * Ss; i += 256)
        is[i >> 6][i & 63] = infl[(size_t)(b * Nn + n0 + (i >> 6)) * Ss + (i & 63)];
    __syncthreads();

    float acc[8][4];
#pragma unroll
    for (int tk = 0; tk < 8; tk++)
#pragma unroll
        for (int i = 0; i < 4; i++) acc[tk][i] = 0.f;

    for (int s = 0; s < Ss; s++) {
        float w0 = is[0][s], w1 = is[1][s], w2 = is[2][s], w3 = is[3][s];
        float w4 = is[4][s], w5 = is[5][s], w6 = is[6][s], w7 = is[7][s];
        if ((w0 != 0.f) | (w1 != 0.f) | (w2 != 0.f) | (w3 != 0.f) |
            (w4 != 0.f) | (w5 != 0.f) | (w6 != 0.f) | (w7 != 0.f)) {
            const float* dr = &dec[(size_t)(b * Ss + s) * Dd];
#pragma unroll
            for (int i = 0; i < 4; i++) {
                float dv = dr[tid + 256 * i];
                acc[0][i] += w0 * dv; acc[1][i] += w1 * dv;
                acc[2][i] += w2 * dv; acc[3][i] += w3 * dv;
                acc[4][i] += w4 * dv; acc[5][i] += w5 * dv;
                acc[6][i] += w6 * dv; acc[7][i] += w7 * dv;
            }
        }
    }

#pragma unroll
    for (int tk = 0; tk < 8; tk++) {
#pragma unroll
        for (int i = 0; i < 4; i++) {
            size_t idx = (size_t)(b * Nn + n0 + tk) * Dd + tid + 256 * i;
            blend[idx] = 0.6f * stdo[idx] + 0.4f * acc[tk][i] * gate[idx];
        }
    }
}

// ============================================================
extern "C" void kernel_launch(void* const* d_in, const int* in_sizes, int n_in,
                              void* d_out, int out_size)
{
    const float* x    = (const float*)d_in[0];
    const float* Wq   = (const float*)d_in[1];
    const float* Wk   = (const float*)d_in[2];
    const float* Wv   = (const float*)d_in[3];
    const float* Wo   = (const float*)d_in[4];
    const float* sp   = (const float*)d_in[5];
    const float* ssc  = (const float*)d_in[6];
    const float* simp = (const float*)d_in[7];
    const float* We   = (const float*)d_in[8];
    const float* be   = (const float*)d_in[9];
    const float* Wt   = (const float*)d_in[10];
    const float* bt   = (const float*)d_in[11];
    const float* Wd   = (const float*)d_in[12];
    const float* bd   = (const float*)d_in[13];
    const float* Wg   = (const float*)d_in[14];
    const float* bg   = (const float*)d_in[15];

    float *Qp, *Kp, *Vp, *Gp, *Stdp, *Inflp, *Totp, *Gathp, *Encp, *Transp, *Decp, *Blendp;
    cudaGetSymbolAddress((void**)&Qp, g_Q);
    cudaGetSymbolAddress((void**)&Kp, g_K);
    cudaGetSymbolAddress((void**)&Vp, g_V);
    cudaGetSymbolAddress((void**)&Gp, g_G);
    cudaGetSymbolAddress((void**)&Stdp, g_std);
    cudaGetSymbolAddress((void**)&Inflp, g_infl);
    cudaGetSymbolAddress((void**)&Totp, g_total);
    cudaGetSymbolAddress((void**)&Gathp, g_gath);
    cudaGetSymbolAddress((void**)&Encp, g_enc);
    cudaGetSymbolAddress((void**)&Transp, g_trans);
    cudaGetSymbolAddress((void**)&Decp, g_dec);
    cudaGetSymbolAddress((void**)&Blendp, g_blend);

    const int M = Bb * Nn;   // 2048

    // ---- fused Q/K/V/Gate projection: Q,K,G 1-pass; V 2-pass ----
    {
        GArgs a;
        a.A = x; a.K = Dd; a.segN = Dd;
        a.B[0] = Wq; a.B[1] = Wk; a.B[2] = Wv; a.B[3] = Wg;
        a.bias[0] = nullptr; a.bias[1] = nullptr; a.bias[2] = nullptr; a.bias[3] = bg;
        a.C[0] = Qp; a.C[1] = Kp; a.C[2] = Vp; a.C[3] = Gp;
        a.epi[0] = 0; a.epi[1] = 0; a.epi[2] = 0; a.epi[3] = 1;
        a.np[0] = 1; a.np[1] = 1; a.np[2] = 2; a.np[3] = 1;
        tf32_gemm<<<dim3(32, M / 128), 256>>>(a);
    }

    attn_mma_kernel<<<dim3(Nn / 128, Bb * Hh), 256>>>(Qp, Kp, Vp, Stdp);

    infl_kernel<<<dim3(Nn / 4, Bb), 256>>>(x, sp, ssc, simp, Inflp);
    total_kernel<<<dim3(Ss, Bb), 256>>>(Inflp, Totp);
    gather_kernel<<<dim3(Ss, Bb), 256>>>(x, Inflp, Totp, Gathp);

    // enc (flow branch): single-pass
    {
        GArgs a;
        a.A = Gathp; a.K = Dd; a.segN = DbC;
        for (int i = 0; i < 4; i++) { a.B[i] = We; a.bias[i] = be; a.C[i] = Encp; a.epi[i] = 2; a.np[i] = 1; }
        tf32_gemm<<<dim3(DbC / 128, 1), 256>>>(a);
    }

    trans_kernel<<<dim3(Ss, DbC / 128), 128>>>(Encp, Wt, bt, Transp);

    // dec (flow branch): single-pass
    {
        GArgs a;
        a.A = Transp; a.K = DbC; a.segN = Dd;
        for (int i = 0; i < 4; i++) { a.B[i] = Wd; a.bias[i] = bd; a.C[i] = Decp; a.epi[i] = 3; a.np[i] = 1; }
        tf32_gemm<<<dim3(Dd / 128, 1), 256>>>(a);
    }

    flow_blend_kernel<<<dim3(Nn / 8, Bb), 256>>>(Inflp, Decp, Gp, Stdp, Blendp);

    // final projection: 2-pass (blend split exact, Wo rounded)
    {
        GArgs a;
        a.A = Blendp; a.K = Dd; a.segN = Dd;
        for (int i = 0; i < 4; i++) { a.B[i] = Wo; a.bias[i] = nullptr; a.C[i] = (float*)d_out; a.epi[i] = 0; a.np[i] = 2; }
        tf32_gemm<<<dim3(Dd / 128, M / 128), 256>>>(a);
    }
}